// round 14
// baseline (speedup 1.0000x reference)
#include <cuda_runtime.h>
#include <cuda_bf16.h>
#include <cstdint>

#define DIM   2048
#define BATCH 32768
#define RCAP1 8192
#define RCAP2 256
#define NSTG  6              // pipeline depth for 1-product kernel
#define NSF   3              // pipeline depth for fused 3-product kernel

// ---------------------------------------------------------------------------
// Device-global scratch
// ---------------------------------------------------------------------------
__device__ __align__(16) float g_H[(size_t)BATCH * DIM];
__device__ __align__(16) __nv_bfloat16 g_Hb[(size_t)BATCH * DIM];   // tier-0 bf16 H
__device__ __align__(16) float g_logits[BATCH * 2];
__device__ __align__(16) __nv_bfloat16 g_xs[2][(size_t)BATCH * DIM];
__device__ __align__(16) __nv_bfloat16 g_ws[2][(size_t)DIM * DIM];
__device__ __align__(16) float g_Hr[(size_t)RCAP2 * DIM];
__device__ int g_idx[2][BATCH];
__device__ int g_cnt[2];
__device__ int g_rlist1[RCAP1];
__device__ int g_rcnt1[1];
__device__ int g_rlist2[RCAP2];
__device__ int g_rcnt2[1];

// ---------------------------------------------------------------------------
// helpers
// ---------------------------------------------------------------------------
__device__ __forceinline__ uint32_t smem_u32_of(const void* p) {
    uint32_t a;
    asm("{ .reg .u64 t; cvta.to.shared.u64 t, %1; cvt.u32.u64 %0, t; }" : "=r"(a) : "l"(p));
    return a;
}
__device__ __forceinline__ void cp16(uint32_t dst, const void* src) {
    asm volatile("cp.async.cg.shared.global [%0], [%1], 16;" :: "r"(dst), "l"(src));
}
__device__ __forceinline__ void ldsm_x4(uint32_t* r, uint32_t addr) {
    asm volatile("ldmatrix.sync.aligned.m8n8.x4.shared.b16 {%0,%1,%2,%3}, [%4];"
                 : "=r"(r[0]), "=r"(r[1]), "=r"(r[2]), "=r"(r[3]) : "r"(addr));
}
__device__ __forceinline__ void mma16816(float* c, const uint32_t* a,
                                         uint32_t b0, uint32_t b1) {
    asm volatile("mma.sync.aligned.m16n8k16.row.col.f32.bf16.bf16.f32 "
                 "{%0,%1,%2,%3}, {%4,%5,%6,%7}, {%8,%9}, {%0,%1,%2,%3};"
                 : "+f"(c[0]), "+f"(c[1]), "+f"(c[2]), "+f"(c[3])
                 : "r"(a[0]), "r"(a[1]), "r"(a[2]), "r"(a[3]), "r"(b0), "r"(b1));
}
__device__ __forceinline__ uint32_t swz(uint32_t off) {       // Swizzle<3,4,3>
    return off ^ (((off >> 7) & 7u) << 4);
}

// ---------------------------------------------------------------------------
// 1-product bf16 GEMM (tier-0 routing): Hb = bf16(A_hi @ B_hi^T + bias)
// ---------------------------------------------------------------------------
__global__ __launch_bounds__(256)
void gemm_mma1(const __nv_bfloat16* __restrict__ Ah,
               const __nv_bfloat16* __restrict__ Bh,
               const float* __restrict__ bias, __nv_bfloat16* __restrict__ Hb)
{
    constexpr int KT    = DIM / 32;
    constexpr int STAGE = 16384;

    extern __shared__ __align__(128) char smem[];
    const uint32_t sbase = smem_u32_of(smem);

    const int tid = threadIdx.x;
    const int wid = tid >> 5, lid = tid & 31;
    const int wm  = wid >> 2;
    const int wn  = wid & 3;
    const int m0  = blockIdx.y * 128;
    const int n0  = blockIdx.x * 128;

    const int lrow = tid >> 2;
    const int lch  = tid & 3;

    const size_t aoff0 = (size_t)(m0 + lrow) * DIM;
    const size_t aoff1 = (size_t)(m0 + lrow + 64) * DIM;
    const size_t boff0 = (size_t)(n0 + lrow) * DIM;
    const size_t boff1 = (size_t)(n0 + lrow + 64) * DIM;

    auto load_stage = [&](int kt, int buf) {
        const size_t kofs = (size_t)kt * 32 + lch * 8;
        const uint32_t sa = sbase + buf * STAGE;
        const uint32_t sb = sa + 8192;
        cp16(sa + swz((uint32_t)lrow * 64 + lch * 16),        Ah + aoff0 + kofs);
        cp16(sa + swz((uint32_t)(lrow + 64) * 64 + lch * 16), Ah + aoff1 + kofs);
        cp16(sb + swz((uint32_t)lrow * 64 + lch * 16),        Bh + boff0 + kofs);
        cp16(sb + swz((uint32_t)(lrow + 64) * 64 + lch * 16), Bh + boff1 + kofs);
        asm volatile("cp.async.commit_group;" ::: "memory");
    };

    float acc[4][4][4];
#pragma unroll
    for (int i = 0; i < 4; i++)
#pragma unroll
        for (int j = 0; j < 4; j++)
#pragma unroll
            for (int r = 0; r < 4; r++) acc[i][j][r] = 0.f;

    const uint32_t a_row = wm * 64 + (lid & 7) + ((lid >> 3) & 1) * 8;
    const uint32_t a_kb  = ((lid >> 4) & 1) * 16;
    const uint32_t b_row = wn * 32 + (lid & 7) + ((lid >> 4) & 1) * 8;
    const uint32_t b_kb  = ((lid >> 3) & 1) * 16;

#pragma unroll
    for (int s = 0; s < NSTG - 1; s++) load_stage(s, s);

    int buf = 0, nbuf = NSTG - 1;
    for (int t = 0; t < KT; t++) {
        asm volatile("cp.async.wait_group %0;" :: "n"(NSTG - 2) : "memory");
        __syncthreads();

        const uint32_t sa = sbase + buf * STAGE;
        const uint32_t sb = sa + 8192;

#pragma unroll
        for (int ks = 0; ks < 2; ks++) {
            uint32_t af[4][4], bf[2][4];
#pragma unroll
            for (int mf = 0; mf < 4; mf++)
                ldsm_x4(af[mf], sa + swz((a_row + mf * 16) * 64 + ks * 32 + a_kb));
#pragma unroll
            for (int ng = 0; ng < 2; ng++)
                ldsm_x4(bf[ng], sb + swz((b_row + ng * 16) * 64 + ks * 32 + b_kb));
#pragma unroll
            for (int mf = 0; mf < 4; mf++)
#pragma unroll
                for (int nf = 0; nf < 4; nf++)
                    mma16816(acc[mf][nf], af[mf],
                             bf[nf >> 1][(nf & 1) * 2], bf[nf >> 1][(nf & 1) * 2 + 1]);
        }

        if (t + NSTG - 1 < KT) load_stage(t + NSTG - 1, nbuf);
        if (++buf == NSTG) buf = 0;
        if (++nbuf == NSTG) nbuf = 0;
    }

    const int er = lid >> 2;
    const int ec = (lid & 3) * 2;
#pragma unroll
    for (int mf = 0; mf < 4; mf++) {
#pragma unroll
        for (int nf = 0; nf < 4; nf++) {
            const int col = n0 + wn * 32 + nf * 8 + ec;
            const float bx = __ldg(&bias[col]);
            const float by = __ldg(&bias[col + 1]);
            const int r0 = m0 + wm * 64 + mf * 16 + er;
            const int r1 = r0 + 8;
            __nv_bfloat162 h0 = __floats2bfloat162_rn(acc[mf][nf][0] + bx, acc[mf][nf][1] + by);
            __nv_bfloat162 h1 = __floats2bfloat162_rn(acc[mf][nf][2] + bx, acc[mf][nf][3] + by);
            *(__nv_bfloat162*)(Hb + (size_t)r0 * DIM + col) = h0;
            *(__nv_bfloat162*)(Hb + (size_t)r1 * DIM + col) = h1;
        }
    }
}

// ---------------------------------------------------------------------------
// FUSED 3-product bf16 GEMM: per k-tile load A_hi/A_mid/B_hi/B_mid once,
// accumulate hh + hm + mh. Tile 128x128, 8 warps, NSF stages, 2 CTAs/SM.
// ---------------------------------------------------------------------------
template<bool GATHER>
__global__ __launch_bounds__(256, 2)
void gemm_mma3f(const __nv_bfloat16* __restrict__ Ah, const __nv_bfloat16* __restrict__ Am,
                const __nv_bfloat16* __restrict__ Bh, const __nv_bfloat16* __restrict__ Bm,
                const float* __restrict__ bias, float* __restrict__ C,
                const int* __restrict__ idx, const int* __restrict__ cnt_p)
{
    constexpr int KT    = DIM / 32;
    constexpr int STAGE = 32768;

    extern __shared__ __align__(128) char smem[];
    __shared__ int sidx[128];
    const uint32_t sbase = smem_u32_of(smem);

    const int tid = threadIdx.x;
    const int wid = tid >> 5, lid = tid & 31;
    const int wm  = wid >> 2;
    const int wn  = wid & 3;
    const int m0  = blockIdx.y * 128;
    const int n0  = blockIdx.x * 128;

    if (GATHER) {
        const int cnt = __ldg(cnt_p);
        if (m0 >= cnt) return;
        if (tid < 128) sidx[tid] = __ldg(&idx[min(m0 + tid, cnt - 1)]);
        __syncthreads();
    }

    const int lrow = tid >> 2;
    const int lch  = tid & 3;

    const int ar0 = GATHER ? sidx[lrow]      : (m0 + lrow);
    const int ar1 = GATHER ? sidx[lrow + 64] : (m0 + lrow + 64);
    const size_t aoff0 = (size_t)ar0 * DIM;
    const size_t aoff1 = (size_t)ar1 * DIM;
    const size_t boff0 = (size_t)(n0 + lrow) * DIM;
    const size_t boff1 = (size_t)(n0 + lrow + 64) * DIM;

    auto load_stage = [&](int kt, int buf) {
        const size_t kofs = (size_t)kt * 32 + lch * 8;
        const uint32_t s0 = sbase + buf * STAGE;
        const uint32_t s1 = s0 + 8192;
        const uint32_t s2 = s0 + 16384;
        const uint32_t s3 = s0 + 24576;
        const uint32_t o0 = swz((uint32_t)lrow * 64 + lch * 16);
        const uint32_t o1 = swz((uint32_t)(lrow + 64) * 64 + lch * 16);
        cp16(s0 + o0, Ah + aoff0 + kofs);
        cp16(s0 + o1, Ah + aoff1 + kofs);
        cp16(s1 + o0, Am + aoff0 + kofs);
        cp16(s1 + o1, Am + aoff1 + kofs);
        cp16(s2 + o0, Bh + boff0 + kofs);
        cp16(s2 + o1, Bh + boff1 + kofs);
        cp16(s3 + o0, Bm + boff0 + kofs);
        cp16(s3 + o1, Bm + boff1 + kofs);
        asm volatile("cp.async.commit_group;" ::: "memory");
    };

    float acc[4][4][4];
#pragma unroll
    for (int i = 0; i < 4; i++)
#pragma unroll
        for (int j = 0; j < 4; j++)
#pragma unroll
            for (int r = 0; r < 4; r++) acc[i][j][r] = 0.f;

    const uint32_t a_row = wm * 64 + (lid & 7) + ((lid >> 3) & 1) * 8;
    const uint32_t a_kb  = ((lid >> 4) & 1) * 16;
    const uint32_t b_row = wn * 32 + (lid & 7) + ((lid >> 4) & 1) * 8;
    const uint32_t b_kb  = ((lid >> 3) & 1) * 16;

#pragma unroll
    for (int s = 0; s < NSF - 1; s++) load_stage(s, s);

    int buf = 0, nbuf = NSF - 1;
    for (int t = 0; t < KT; t++) {
        asm volatile("cp.async.wait_group %0;" :: "n"(NSF - 2) : "memory");
        __syncthreads();

        const uint32_t sAh = sbase + buf * STAGE;
        const uint32_t sAm = sAh + 8192;
        const uint32_t sBh = sAh + 16384;
        const uint32_t sBm = sAh + 24576;

#pragma unroll
        for (int ks = 0; ks < 2; ks++) {
            uint32_t bh[2][4], bm[2][4];
#pragma unroll
            for (int ng = 0; ng < 2; ng++) {
                ldsm_x4(bh[ng], sBh + swz((b_row + ng * 16) * 64 + ks * 32 + b_kb));
                ldsm_x4(bm[ng], sBm + swz((b_row + ng * 16) * 64 + ks * 32 + b_kb));
            }
#pragma unroll
            for (int mf = 0; mf < 4; mf++) {
                uint32_t a[4];
                ldsm_x4(a, sAh + swz((a_row + mf * 16) * 64 + ks * 32 + a_kb));
#pragma unroll
                for (int nf = 0; nf < 4; nf++)
                    mma16816(acc[mf][nf], a,
                             bh[nf >> 1][(nf & 1) * 2], bh[nf >> 1][(nf & 1) * 2 + 1]);
#pragma unroll
                for (int nf = 0; nf < 4; nf++)
                    mma16816(acc[mf][nf], a,
                             bm[nf >> 1][(nf & 1) * 2], bm[nf >> 1][(nf & 1) * 2 + 1]);
            }
#pragma unroll
            for (int mf = 0; mf < 4; mf++) {
                uint32_t a[4];
                ldsm_x4(a, sAm + swz((a_row + mf * 16) * 64 + ks * 32 + a_kb));
#pragma unroll
                for (int nf = 0; nf < 4; nf++)
                    mma16816(acc[mf][nf], a,
                             bh[nf >> 1][(nf & 1) * 2], bh[nf >> 1][(nf & 1) * 2 + 1]);
            }
        }

        if (t + NSF - 1 < KT) load_stage(t + NSF - 1, nbuf);
        if (++buf == NSF) buf = 0;
        if (++nbuf == NSF) nbuf = 0;
    }

    const int er = lid >> 2;
    const int ec = (lid & 3) * 2;
#pragma unroll
    for (int mf = 0; mf < 4; mf++) {
#pragma unroll
        for (int nf = 0; nf < 4; nf++) {
            const int col = n0 + wn * 32 + nf * 8 + ec;
            const float bx = __ldg(&bias[col]);
            const float by = __ldg(&bias[col + 1]);
            const int r0 = m0 + wm * 64 + mf * 16 + er;
            const int r1 = r0 + 8;
            *(float2*)(C + (size_t)r0 * DIM + col) = make_float2(acc[mf][nf][0] + bx, acc[mf][nf][1] + by);
            *(float2*)(C + (size_t)r1 * DIM + col) = make_float2(acc[mf][nf][2] + bx, acc[mf][nf][3] + by);
        }
    }
}

// ---------------------------------------------------------------------------
// fp32 -> 2-way bf16 split
// ---------------------------------------------------------------------------
__global__ __launch_bounds__(256)
void split2_kernel(const float* __restrict__ in, __nv_bfloat16* __restrict__ h,
                   __nv_bfloat16* __restrict__ m, size_t n)
{
    size_t i = ((size_t)blockIdx.x * 256 + threadIdx.x) * 4;
    if (i >= n) return;
    float4 v = *(const float4*)(in + i);
    float vv[4] = {v.x, v.y, v.z, v.w};
    __nv_bfloat16 hh[4], mm[4];
#pragma unroll
    for (int j = 0; j < 4; j++) {
        float x = vv[j];
        __nv_bfloat16 a = __float2bfloat16(x);
        float r = x - __bfloat162float(a);
        mm[j] = __float2bfloat16(r);
        hh[j] = a;
    }
    *(__nv_bfloat162*)(h + i)     = __nv_bfloat162(hh[0], hh[1]);
    *(__nv_bfloat162*)(h + i + 2) = __nv_bfloat162(hh[2], hh[3]);
    *(__nv_bfloat162*)(m + i)     = __nv_bfloat162(mm[0], mm[1]);
    *(__nv_bfloat162*)(m + i + 2) = __nv_bfloat162(mm[2], mm[3]);
}

// ---------------------------------------------------------------------------
// block reductions (256 threads): 2-float and 4-float variants
// ---------------------------------------------------------------------------
__device__ __forceinline__ float2 block_reduce2(float a, float b)
{
    __shared__ float sa[8], sb[8];
    __syncthreads();
    int lane = threadIdx.x & 31, wd = threadIdx.x >> 5;
#pragma unroll
    for (int o = 16; o; o >>= 1) {
        a += __shfl_down_sync(0xFFFFFFFFu, a, o);
        b += __shfl_down_sync(0xFFFFFFFFu, b, o);
    }
    if (lane == 0) { sa[wd] = a; sb[wd] = b; }
    __syncthreads();
    if (wd == 0) {
        a = (lane < 8) ? sa[lane] : 0.f;
        b = (lane < 8) ? sb[lane] : 0.f;
#pragma unroll
        for (int o = 4; o; o >>= 1) {
            a += __shfl_down_sync(0xFFFFFFFFu, a, o);
            b += __shfl_down_sync(0xFFFFFFFFu, b, o);
        }
        if (lane == 0) { sa[0] = a; sb[0] = b; }
    }
    __syncthreads();
    return make_float2(sa[0], sb[0]);
}

__device__ __forceinline__ float4 block_reduce4(float a, float b, float c, float d)
{
    __shared__ float sm4[4][8];
    __syncthreads();
    int lane = threadIdx.x & 31, wd = threadIdx.x >> 5;
#pragma unroll
    for (int o = 16; o; o >>= 1) {
        a += __shfl_down_sync(0xFFFFFFFFu, a, o);
        b += __shfl_down_sync(0xFFFFFFFFu, b, o);
        c += __shfl_down_sync(0xFFFFFFFFu, c, o);
        d += __shfl_down_sync(0xFFFFFFFFu, d, o);
    }
    if (lane == 0) { sm4[0][wd] = a; sm4[1][wd] = b; sm4[2][wd] = c; sm4[3][wd] = d; }
    __syncthreads();
    if (wd == 0) {
        a = (lane < 8) ? sm4[0][lane] : 0.f;
        b = (lane < 8) ? sm4[1][lane] : 0.f;
        c = (lane < 8) ? sm4[2][lane] : 0.f;
        d = (lane < 8) ? sm4[3][lane] : 0.f;
#pragma unroll
        for (int o = 4; o; o >>= 1) {
            a += __shfl_down_sync(0xFFFFFFFFu, a, o);
            b += __shfl_down_sync(0xFFFFFFFFu, b, o);
            c += __shfl_down_sync(0xFFFFFFFFu, c, o);
            d += __shfl_down_sync(0xFFFFFFFFu, d, o);
        }
        if (lane == 0) { sm4[0][0] = a; sm4[1][0] = b; sm4[2][0] = c; sm4[3][0] = d; }
    }
    __syncthreads();
    return make_float4(sm4[0][0], sm4[1][0], sm4[2][0], sm4[3][0]);
}

// ---------------------------------------------------------------------------
// per-row head math (params already in registers at call sites)
// ---------------------------------------------------------------------------
struct LnParams {
    float4 ga, gb, ba, bb, wa, wb, wc, wd;
    float bias0, bias1;
};

__device__ __forceinline__ void head_row(const LnParams& P, float4 v0, float4 v1,
                                         float mu, float rinv, float& l0, float& l1)
{
    float h;
    l0 = 0.f; l1 = 0.f;
    h = fmaxf(fmaf((v0.x - mu)*rinv, P.ga.x, P.ba.x), 0.f); l0 += h*P.wa.x; l1 += h*P.wc.x;
    h = fmaxf(fmaf((v0.y - mu)*rinv, P.ga.y, P.ba.y), 0.f); l0 += h*P.wa.y; l1 += h*P.wc.y;
    h = fmaxf(fmaf((v0.z - mu)*rinv, P.ga.z, P.ba.z), 0.f); l0 += h*P.wa.z; l1 += h*P.wc.z;
    h = fmaxf(fmaf((v0.w - mu)*rinv, P.ga.w, P.ba.w), 0.f); l0 += h*P.wa.w; l1 += h*P.wc.w;
    h = fmaxf(fmaf((v1.x - mu)*rinv, P.gb.x, P.bb.x), 0.f); l0 += h*P.wb.x; l1 += h*P.wd.x;
    h = fmaxf(fmaf((v1.y - mu)*rinv, P.gb.y, P.bb.y), 0.f); l0 += h*P.wb.y; l1 += h*P.wd.y;
    h = fmaxf(fmaf((v1.z - mu)*rinv, P.gb.z, P.bb.z), 0.f); l0 += h*P.wb.z; l1 += h*P.wd.z;
    h = fmaxf(fmaf((v1.w - mu)*rinv, P.gb.w, P.bb.w), 0.f); l0 += h*P.wb.w; l1 += h*P.wd.w;
}

__device__ __forceinline__ LnParams load_params(const float* gamma, const float* beta,
                                                const float* W2, const float* b2, int t)
{
    LnParams P;
    P.ga = ((const float4*)gamma)[t*2]; P.gb = ((const float4*)gamma)[t*2+1];
    P.ba = ((const float4*)beta)[t*2];  P.bb = ((const float4*)beta)[t*2+1];
    P.wa = ((const float4*)W2)[t*2];    P.wb = ((const float4*)W2)[t*2+1];
    P.wc = ((const float4*)(W2+DIM))[t*2]; P.wd = ((const float4*)(W2+DIM))[t*2+1];
    P.bias0 = __ldg(&b2[0]); P.bias1 = __ldg(&b2[1]);
    return P;
}

// ---------------------------------------------------------------------------
// LN + ReLU + head, 8 rows/block, row-PAIR batched reductions, prefetch.
// fp32 H version (tier-1 patch + value branches).
// ---------------------------------------------------------------------------
template<bool SCATTER>
__global__ __launch_bounds__(256)
void ln_head8(const float* __restrict__ H,
              const float* __restrict__ gamma, const float* __restrict__ beta,
              const float* __restrict__ W2, const float* __restrict__ b2,
              const int* __restrict__ idx, const int* __restrict__ cnt_p,
              float* __restrict__ out)
{
    const int base = blockIdx.x * 8;
    int cnt = BATCH;
    if (SCATTER) {
        cnt = __ldg(cnt_p);
        if (base >= cnt) return;
    }
    const int t = threadIdx.x;
    const LnParams P = load_params(gamma, beta, W2, b2, t);
    const float inv_d = 1.f / (float)DIM;

    auto rowptr = [&](int row) {
        const int rr = SCATTER ? min(row, cnt - 1) : row;
        return (const float4*)(H + (size_t)rr * DIM);
    };

    float4 a0 = rowptr(base)[t*2],     a1 = rowptr(base)[t*2+1];
    float4 b0 = rowptr(base+1)[t*2],   b1 = rowptr(base+1)[t*2+1];

#pragma unroll 1
    for (int r = 0; r < 8; r += 2) {
        float sA  = a0.x+a0.y+a0.z+a0.w + a1.x+a1.y+a1.z+a1.w;
        float ssA = a0.x*a0.x+a0.y*a0.y+a0.z*a0.z+a0.w*a0.w
                  + a1.x*a1.x+a1.y*a1.y+a1.z*a1.z+a1.w*a1.w;
        float sB  = b0.x+b0.y+b0.z+b0.w + b1.x+b1.y+b1.z+b1.w;
        float ssB = b0.x*b0.x+b0.y*b0.y+b0.z*b0.z+b0.w*b0.w
                  + b1.x*b1.x+b1.y*b1.y+b1.z*b1.z+b1.w*b1.w;

        float4 n0a, n1a, n0b, n1b;
        if (r < 6) {
            n0a = rowptr(base+r+2)[t*2]; n1a = rowptr(base+r+2)[t*2+1];
            n0b = rowptr(base+r+3)[t*2]; n1b = rowptr(base+r+3)[t*2+1];
        }

        float4 red = block_reduce4(sA, ssA, sB, ssB);
        float muA = red.x * inv_d, varA = red.y * inv_d - muA * muA;
        float muB = red.z * inv_d, varB = red.w * inv_d - muB * muB;
        float rinvA = rsqrtf(varA + 1e-5f);
        float rinvB = rsqrtf(varB + 1e-5f);

        float l0A, l1A, l0B, l1B;
        head_row(P, a0, a1, muA, rinvA, l0A, l1A);
        head_row(P, b0, b1, muB, rinvB, l0B, l1B);

        float4 lr = block_reduce4(l0A, l1A, l0B, l1B);
        if (t == 0) {
            const int rowA = base + r, rowB = base + r + 1;
            if (!SCATTER || rowA < cnt) {
                const int oA = SCATTER ? __ldg(&idx[rowA]) : rowA;
                out[oA*2]   = lr.x + P.bias0;
                out[oA*2+1] = lr.y + P.bias1;
            }
            if (!SCATTER || rowB < cnt) {
                const int oB = SCATTER ? __ldg(&idx[rowB]) : rowB;
                out[oB*2]   = lr.z + P.bias0;
                out[oB*2+1] = lr.w + P.bias1;
            }
        }
        a0 = n0a; a1 = n1a; b0 = n0b; b1 = n1b;
    }
}

// bf16-H version (tier-0 routing logits only)
__global__ __launch_bounds__(256)
void ln_head8_bf(const __nv_bfloat16* __restrict__ Hb,
                 const float* __restrict__ gamma, const float* __restrict__ beta,
                 const float* __restrict__ W2, const float* __restrict__ b2,
                 float* __restrict__ out)
{
    const int base = blockIdx.x * 8;
    const int t = threadIdx.x;
    const LnParams P = load_params(gamma, beta, W2, b2, t);
    const float inv_d = 1.f / (float)DIM;

    auto loadrow = [&](int row, float4& v0, float4& v1) {
        // 8 bf16 = 16B per thread
        uint4 u = *(const uint4*)(Hb + (size_t)row * DIM + t * 8);
        float2 p0 = __bfloat1622float2(*(__nv_bfloat162*)&u.x);
        float2 p1 = __bfloat1622float2(*(__nv_bfloat162*)&u.y);
        float2 p2 = __bfloat1622float2(*(__nv_bfloat162*)&u.z);
        float2 p3 = __bfloat1622float2(*(__nv_bfloat162*)&u.w);
        v0 = make_float4(p0.x, p0.y, p1.x, p1.y);
        v1 = make_float4(p2.x, p2.y, p3.x, p3.y);
    };

    float4 a0, a1, b0, b1;
    loadrow(base, a0, a1);
    loadrow(base + 1, b0, b1);

#pragma unroll 1
    for (int r = 0; r < 8; r += 2) {
        float sA  = a0.x+a0.y+a0.z+a0.w + a1.x+a1.y+a1.z+a1.w;
        float ssA = a0.x*a0.x+a0.y*a0.y+a0.z*a0.z+a0.w*a0.w
                  + a1.x*a1.x+a1.y*a1.y+a1.z*a1.z+a1.w*a1.w;
        float sB  = b0.x+b0.y+b0.z+b0.w + b1.x+b1.y+b1.z+b1.w;
        float ssB = b0.x*b0.x+b0.y*b0.y+b0.z*b0.z+b0.w*b0.w
                  + b1.x*b1.x+b1.y*b1.y+b1.z*b1.z+b1.w*b1.w;

        float4 n0a, n1a, n0b, n1b;
        if (r < 6) {
            loadrow(base + r + 2, n0a, n1a);
            loadrow(base + r + 3, n0b, n1b);
        }

        float4 red = block_reduce4(sA, ssA, sB, ssB);
        float muA = red.x * inv_d, varA = red.y * inv_d - muA * muA;
        float muB = red.z * inv_d, varB = red.w * inv_d - muB * muB;
        float rinvA = rsqrtf(varA + 1e-5f);
        float rinvB = rsqrtf(varB + 1e-5f);

        float l0A, l1A, l0B, l1B;
        head_row(P, a0, a1, muA, rinvA, l0A, l1A);
        head_row(P, b0, b1, muB, rinvB, l0B, l1B);

        float4 lr = block_reduce4(l0A, l1A, l0B, l1B);
        if (t == 0) {
            const int rowA = base + r, rowB = base + r + 1;
            out[rowA*2]   = lr.x + P.bias0;
            out[rowA*2+1] = lr.y + P.bias1;
            out[rowB*2]   = lr.z + P.bias0;
            out[rowB*2+1] = lr.w + P.bias1;
        }
        a0 = n0a; a1 = n1a; b0 = n0b; b1 = n1b;
    }
}

// ---------------------------------------------------------------------------
// Flag rows with |l0-l1| < thresh. Single block, ordered compaction.
// ---------------------------------------------------------------------------
__global__ __launch_bounds__(1024)
void flag_scan(const float* __restrict__ L0, float thresh, int cap,
               int* __restrict__ rlist, int* __restrict__ rcnt)
{
    __shared__ int sf[1024];
    const int t = threadIdx.x;
    uint32_t mask = 0;
    int c = 0;
#pragma unroll
    for (int j = 0; j < 32; j++) {
        const int b = t * 32 + j;
        float2 f = ((const float2*)L0)[b];
        const bool fl = fabsf(f.x - f.y) < thresh;
        mask |= (uint32_t)fl << j;
        c += fl;
    }
    sf[t] = c;
    __syncthreads();
    for (int off = 1; off < 1024; off <<= 1) {
        int v = (t >= off) ? sf[t - off] : 0;
        __syncthreads();
        sf[t] += v;
        __syncthreads();
    }
    int pos = sf[t] - c;
#pragma unroll
    for (int j = 0; j < 32; j++) {
        if ((mask >> j) & 1) {
            if (pos < cap) rlist[pos] = t * 32 + j;
            pos++;
        }
    }
    if (t == 1023) rcnt[0] = min(sf[1023], cap);
}

// ---------------------------------------------------------------------------
// Exact fp32 recompute of h = x@W1.T + b1 for flagged rows (column-parallel).
// ---------------------------------------------------------------------------
__global__ __launch_bounds__(256)
void refine_h(const float* __restrict__ x, const float* __restrict__ W1,
              const float* __restrict__ b1,
              const int* __restrict__ rlist, const int* __restrict__ rcnt,
              float* __restrict__ Hr)
{
    const int slot = blockIdx.y;
    if (slot >= __ldg(rcnt)) return;
    const int row = __ldg(&rlist[slot]);

    __shared__ float sx[DIM];
    const int tid = threadIdx.x, wid = tid >> 5, lane = tid & 31;
    for (int i = tid; i < DIM; i += 256) sx[i] = x[(size_t)row * DIM + i];
    __syncthreads();

    const int col0 = blockIdx.x * 64;
#pragma unroll 1
    for (int c = wid; c < 64; c += 8) {
        const int j = col0 + c;
        const float* wr = W1 + (size_t)j * DIM;
        float acc = 0.f;
#pragma unroll 8
        for (int k = lane; k < DIM; k += 32)
            acc = fmaf(sx[k], __ldg(&wr[k]), acc);
#pragma unroll
        for (int o = 16; o; o >>= 1) acc += __shfl_down_sync(0xFFFFFFFFu, acc, o);
        if (lane == 0) Hr[(size_t)slot * DIM + j] = acc + __ldg(&b1[j]);
    }
}

// LN + head from exact h; patch L[row]. One block per slot.
__global__ __launch_bounds__(256)
void refine_fix(const float* __restrict__ Hr,
                const float* __restrict__ gamma, const float* __restrict__ beta,
                const float* __restrict__ W2, const float* __restrict__ b2,
                const int* __restrict__ rlist, const int* __restrict__ rcnt,
                float* __restrict__ L)
{
    const int slot = blockIdx.x;
    if (slot >= __ldg(rcnt)) return;
    const int t = threadIdx.x;
    const LnParams P = load_params(gamma, beta, W2, b2, t);
    const float4* h4 = (const float4*)(Hr + (size_t)slot * DIM);
    float4 v0 = h4[t*2];
    float4 v1 = h4[t*2+1];

    float s  = v0.x+v0.y+v0.z+v0.w + v1.x+v1.y+v1.z+v1.w;
    float ss = v0.x*v0.x+v0.y*v0.y+v0.z*v0.z+v0.w*v0.w
             + v1.x*v1.x+v1.y*v1.y+v1.z*v1.z+v1.w*v1.w;
    float2 red = block_reduce2(s, ss);
    const float inv_d = 1.f / (float)DIM;
    float mu = red.x * inv_d, var = red.y * inv_d - mu * mu;
    float rinv = rsqrtf(var + 1e-5f);

    float l0, l1;
    head_row(P, v0, v1, mu, rinv, l0, l1);
    float2 lr = block_reduce2(l0, l1);
    if (t == 0) {
        const int row = __ldg(&rlist[slot]);
        L[row*2]   = lr.x + P.bias0;
        L[row*2+1] = lr.y + P.bias1;
    }
}

// ---------------------------------------------------------------------------
// Deterministic route compaction: 1 block, 1024 threads, 32 rows each.
// ---------------------------------------------------------------------------
__global__ __launch_bounds__(1024)
void route_scan(const float* __restrict__ L0, int* __restrict__ fake_idx,
                int* __restrict__ real_idx, int* __restrict__ cnts)
{
    __shared__ int sf[1024];
    const int t = threadIdx.x;
    uint32_t mask = 0;
    int c = 0;
#pragma unroll
    for (int j = 0; j < 32; j++) {
        const int b = t * 32 + j;
        float2 f = ((const float2*)L0)[b];
        const bool fake = (f.x >= f.y);
        mask |= (uint32_t)fake << j;
        c += fake;
    }
    sf[t] = c;
    __syncthreads();
    for (int off = 1; off < 1024; off <<= 1) {
        int v = (t >= off) ? sf[t - off] : 0;
        __syncthreads();
        sf[t] += v;
        __syncthreads();
    }
    const int total_fake = sf[1023];
    const int excl = sf[t] - c;
    int fpos = excl;
#pragma unroll
    for (int j = 0; j < 32; j++) {
        const int b = t * 32 + j;
        if ((mask >> j) & 1) {
            fake_idx[fpos++] = b;
        } else {
            const int fake_before = excl + __popc(mask & ((1u << j) - 1u));
            real_idx[b - fake_before] = b;
        }
    }
    if (t == 0) { cnts[0] = total_fake; cnts[1] = BATCH - total_fake; }
}

// ---------------------------------------------------------------------------
extern "C" void kernel_launch(void* const* d_in, const int* in_sizes, int n_in,
                              void* d_out, int out_size)
{
    (void)in_sizes; (void)n_in; (void)out_size;
    const float* x = (const float*)d_in[0];

    float *H = nullptr, *L = nullptr, *Hr = nullptr;
    __nv_bfloat16 *Hb = nullptr;
    __nv_bfloat16 *xs = nullptr, *ws = nullptr;
    int *idx = nullptr, *cnt = nullptr;
    int *rl1 = nullptr, *rc1 = nullptr, *rl2 = nullptr, *rc2 = nullptr;
    cudaGetSymbolAddress((void**)&H,   g_H);
    cudaGetSymbolAddress((void**)&Hb,  g_Hb);
    cudaGetSymbolAddress((void**)&L,   g_logits);
    cudaGetSymbolAddress((void**)&Hr,  g_Hr);
    cudaGetSymbolAddress((void**)&xs,  g_xs);
    cudaGetSymbolAddress((void**)&ws,  g_ws);
    cudaGetSymbolAddress((void**)&idx, g_idx);
    cudaGetSymbolAddress((void**)&cnt, g_cnt);
    cudaGetSymbolAddress((void**)&rl1, g_rlist1);
    cudaGetSymbolAddress((void**)&rc1, g_rcnt1);
    cudaGetSymbolAddress((void**)&rl2, g_rlist2);
    cudaGetSymbolAddress((void**)&rc2, g_rcnt2);

    const size_t XN = (size_t)BATCH * DIM;
    const size_t WN = (size_t)DIM * DIM;
    __nv_bfloat16 *xh = xs, *xm = xs + XN;
    __nv_bfloat16 *wh = ws, *wm = ws + WN;

    constexpr int SMEM1 = NSTG * 16384;   // 96 KB
    constexpr int SMEM3 = NSF  * 32768;   // 96 KB
    cudaFuncSetAttribute(gemm_mma1,        cudaFuncAttributeMaxDynamicSharedMemorySize, SMEM1);
    cudaFuncSetAttribute(gemm_mma3f<true>, cudaFuncAttributeMaxDynamicSharedMemorySize, SMEM3);

    split2_kernel<<<(int)(XN / 4 / 256), 256>>>(x, xh, xm, XN);

    dim3 grid(DIM / 128, BATCH / 128);        // (16, 256)
    dim3 grid_t1(DIM / 128, RCAP1 / 128);     // (16, 64)

    // ---- first (routing) branch: 1-product bf16-H GEMM + tiered refine ----
    {
        const float* W1 = (const float*)d_in[1];
        const float* b1 = (const float*)d_in[2];
        const float* lg = (const float*)d_in[3];
        const float* lb = (const float*)d_in[4];
        const float* W2 = (const float*)d_in[5];
        const float* b2 = (const float*)d_in[6];
        split2_kernel<<<(int)(WN / 4 / 256), 256>>>(W1, wh, wm, WN);

        // tier-0: 1-product GEMM, bf16 H (gap error sigma ~2.7e-3 incl. bf16-H)
        gemm_mma1<<<grid, 256, SMEM1>>>(xh, wh, b1, Hb);
        ln_head8_bf<<<BATCH / 8, 256>>>(Hb, lg, lb, W2, b2, L);

        // tier-1: |gap| < 2.6e-2 (~10 sigma) -> fused 3-product recompute, patch L
        flag_scan<<<1, 1024>>>(L, 2.6e-2f, RCAP1, rl1, rc1);
        gemm_mma3f<true><<<grid_t1, 256, SMEM3>>>(xh, xm, wh, wm, b1, H, rl1, rc1);
        ln_head8<true><<<RCAP1 / 8, 256>>>(H, lg, lb, W2, b2, rl1, rc1, L);

        // tier-2: |gap| < 1e-3 -> exact fp32 recompute, patch L
        flag_scan<<<1, 1024>>>(L, 1e-3f, RCAP2, rl2, rc2);
        refine_h<<<dim3(32, RCAP2), 256>>>(x, W1, b1, rl2, rc2, Hr);
        refine_fix<<<RCAP2, 256>>>(Hr, lg, lb, W2, b2, rl2, rc2, L);
    }

    route_scan<<<1, 1024>>>(L, idx, idx + BATCH, cnt);

    // ---- fake (route==0) and real branches: fused 3-product, gathered ----
    for (int br = 1; br < 3; br++) {
        const float* W1 = (const float*)d_in[1 + br * 6 + 0];
        const float* b1 = (const float*)d_in[1 + br * 6 + 1];
        const float* lg = (const float*)d_in[1 + br * 6 + 2];
        const float* lb = (const float*)d_in[1 + br * 6 + 3];
        const float* W2 = (const float*)d_in[1 + br * 6 + 4];
        const float* b2 = (const float*)d_in[1 + br * 6 + 5];

        split2_kernel<<<(int)(WN / 4 / 256), 256>>>(W1, wh, wm, WN);

        int* bidx = idx + (br - 1) * BATCH;
        int* bcnt = cnt + (br - 1);
        gemm_mma3f<true><<<grid, 256, SMEM3>>>(xh, xm, wh, wm, b1, H, bidx, bcnt);
        ln_head8<true><<<BATCH / 8, 256>>>(H, lg, lb, W2, b2, bidx, bcnt,
                                           (float*)d_out);
    }
}

// round 15
// speedup vs baseline: 1.0000x; 1.0000x over previous
#include <cuda_runtime.h>
#include <cuda_bf16.h>
#include <cstdint>

#define DIM   2048
#define BATCH 32768
#define RCAP1 8192
#define RCAP2 256
#define NSTG  6              // pipeline depth for 1-product kernel
#define NSF   3              // pipeline depth for fused 3-product kernel

// ---------------------------------------------------------------------------
// Device-global scratch
// ---------------------------------------------------------------------------
__device__ __align__(16) float g_H[(size_t)BATCH * DIM];
__device__ __align__(16) __nv_bfloat16 g_Hb[(size_t)BATCH * DIM];   // tier-0 bf16 H
__device__ __align__(16) float g_logits[BATCH * 2];
__device__ __align__(16) __nv_bfloat16 g_xs[2][(size_t)BATCH * DIM];
__device__ __align__(16) __nv_bfloat16 g_ws[2][(size_t)DIM * DIM];
__device__ __align__(16) float g_Hr[(size_t)RCAP2 * DIM];
__device__ int g_idx[2][BATCH];
__device__ int g_cnt[2];
__device__ int g_rlist1[RCAP1];
__device__ int g_rcnt1[1];
__device__ int g_rlist2[RCAP2];
__device__ int g_rcnt2[1];

// ---------------------------------------------------------------------------
// helpers
// ---------------------------------------------------------------------------
__device__ __forceinline__ uint32_t smem_u32_of(const void* p) {
    uint32_t a;
    asm("{ .reg .u64 t; cvta.to.shared.u64 t, %1; cvt.u32.u64 %0, t; }" : "=r"(a) : "l"(p));
    return a;
}
__device__ __forceinline__ void cp16(uint32_t dst, const void* src) {
    asm volatile("cp.async.cg.shared.global [%0], [%1], 16;" :: "r"(dst), "l"(src));
}
__device__ __forceinline__ void ldsm_x4(uint32_t* r, uint32_t addr) {
    asm volatile("ldmatrix.sync.aligned.m8n8.x4.shared.b16 {%0,%1,%2,%3}, [%4];"
                 : "=r"(r[0]), "=r"(r[1]), "=r"(r[2]), "=r"(r[3]) : "r"(addr));
}
__device__ __forceinline__ void mma16816(float* c, const uint32_t* a,
                                         uint32_t b0, uint32_t b1) {
    asm volatile("mma.sync.aligned.m16n8k16.row.col.f32.bf16.bf16.f32 "
                 "{%0,%1,%2,%3}, {%4,%5,%6,%7}, {%8,%9}, {%0,%1,%2,%3};"
                 : "+f"(c[0]), "+f"(c[1]), "+f"(c[2]), "+f"(c[3])
                 : "r"(a[0]), "r"(a[1]), "r"(a[2]), "r"(a[3]), "r"(b0), "r"(b1));
}
__device__ __forceinline__ uint32_t swz(uint32_t off) {       // Swizzle<3,4,3>
    return off ^ (((off >> 7) & 7u) << 4);
}

// ---------------------------------------------------------------------------
// 1-product bf16 GEMM (tier-0 routing): Hb = bf16(A_hi @ B_hi^T + bias)
// R9-proven config: tile 128x128, 8 warps, NSTG-stage cp.async, 2 CTAs/SM.
// ---------------------------------------------------------------------------
__global__ __launch_bounds__(256)
void gemm_mma1(const __nv_bfloat16* __restrict__ Ah,
               const __nv_bfloat16* __restrict__ Bh,
               const float* __restrict__ bias, __nv_bfloat16* __restrict__ Hb)
{
    constexpr int KT    = DIM / 32;
    constexpr int STAGE = 16384;

    extern __shared__ __align__(128) char smem[];
    const uint32_t sbase = smem_u32_of(smem);

    const int tid = threadIdx.x;
    const int wid = tid >> 5, lid = tid & 31;
    const int wm  = wid >> 2;
    const int wn  = wid & 3;
    const int m0  = blockIdx.y * 128;
    const int n0  = blockIdx.x * 128;

    const int lrow = tid >> 2;
    const int lch  = tid & 3;

    const size_t aoff0 = (size_t)(m0 + lrow) * DIM;
    const size_t aoff1 = (size_t)(m0 + lrow + 64) * DIM;
    const size_t boff0 = (size_t)(n0 + lrow) * DIM;
    const size_t boff1 = (size_t)(n0 + lrow + 64) * DIM;

    auto load_stage = [&](int kt, int buf) {
        const size_t kofs = (size_t)kt * 32 + lch * 8;
        const uint32_t sa = sbase + buf * STAGE;
        const uint32_t sb = sa + 8192;
        cp16(sa + swz((uint32_t)lrow * 64 + lch * 16),        Ah + aoff0 + kofs);
        cp16(sa + swz((uint32_t)(lrow + 64) * 64 + lch * 16), Ah + aoff1 + kofs);
        cp16(sb + swz((uint32_t)lrow * 64 + lch * 16),        Bh + boff0 + kofs);
        cp16(sb + swz((uint32_t)(lrow + 64) * 64 + lch * 16), Bh + boff1 + kofs);
        asm volatile("cp.async.commit_group;" ::: "memory");
    };

    float acc[4][4][4];
#pragma unroll
    for (int i = 0; i < 4; i++)
#pragma unroll
        for (int j = 0; j < 4; j++)
#pragma unroll
            for (int r = 0; r < 4; r++) acc[i][j][r] = 0.f;

    const uint32_t a_row = wm * 64 + (lid & 7) + ((lid >> 3) & 1) * 8;
    const uint32_t a_kb  = ((lid >> 4) & 1) * 16;
    const uint32_t b_row = wn * 32 + (lid & 7) + ((lid >> 4) & 1) * 8;
    const uint32_t b_kb  = ((lid >> 3) & 1) * 16;

#pragma unroll
    for (int s = 0; s < NSTG - 1; s++) load_stage(s, s);

    int buf = 0, nbuf = NSTG - 1;
    for (int t = 0; t < KT; t++) {
        asm volatile("cp.async.wait_group %0;" :: "n"(NSTG - 2) : "memory");
        __syncthreads();

        const uint32_t sa = sbase + buf * STAGE;
        const uint32_t sb = sa + 8192;

#pragma unroll
        for (int ks = 0; ks < 2; ks++) {
            uint32_t af[4][4], bf[2][4];
#pragma unroll
            for (int mf = 0; mf < 4; mf++)
                ldsm_x4(af[mf], sa + swz((a_row + mf * 16) * 64 + ks * 32 + a_kb));
#pragma unroll
            for (int ng = 0; ng < 2; ng++)
                ldsm_x4(bf[ng], sb + swz((b_row + ng * 16) * 64 + ks * 32 + b_kb));
#pragma unroll
            for (int mf = 0; mf < 4; mf++)
#pragma unroll
                for (int nf = 0; nf < 4; nf++)
                    mma16816(acc[mf][nf], af[mf],
                             bf[nf >> 1][(nf & 1) * 2], bf[nf >> 1][(nf & 1) * 2 + 1]);
        }

        if (t + NSTG - 1 < KT) load_stage(t + NSTG - 1, nbuf);
        if (++buf == NSTG) buf = 0;
        if (++nbuf == NSTG) nbuf = 0;
    }

    const int er = lid >> 2;
    const int ec = (lid & 3) * 2;
#pragma unroll
    for (int mf = 0; mf < 4; mf++) {
#pragma unroll
        for (int nf = 0; nf < 4; nf++) {
            const int col = n0 + wn * 32 + nf * 8 + ec;
            const float bx = __ldg(&bias[col]);
            const float by = __ldg(&bias[col + 1]);
            const int r0 = m0 + wm * 64 + mf * 16 + er;
            const int r1 = r0 + 8;
            __nv_bfloat162 h0 = __floats2bfloat162_rn(acc[mf][nf][0] + bx, acc[mf][nf][1] + by);
            __nv_bfloat162 h1 = __floats2bfloat162_rn(acc[mf][nf][2] + bx, acc[mf][nf][3] + by);
            *(__nv_bfloat162*)(Hb + (size_t)r0 * DIM + col) = h0;
            *(__nv_bfloat162*)(Hb + (size_t)r1 * DIM + col) = h1;
        }
    }
}

// ---------------------------------------------------------------------------
// FUSED 3-product bf16 GEMM (R13-proven): per k-tile load A_hi/A_mid/B_hi/B_mid
// once, accumulate hh + hm + mh. Tile 128x128, 8 warps, NSF stages, 2 CTAs/SM.
// ---------------------------------------------------------------------------
template<bool GATHER>
__global__ __launch_bounds__(256, 2)
void gemm_mma3f(const __nv_bfloat16* __restrict__ Ah, const __nv_bfloat16* __restrict__ Am,
                const __nv_bfloat16* __restrict__ Bh, const __nv_bfloat16* __restrict__ Bm,
                const float* __restrict__ bias, float* __restrict__ C,
                const int* __restrict__ idx, const int* __restrict__ cnt_p)
{
    constexpr int KT    = DIM / 32;
    constexpr int STAGE = 32768;

    extern __shared__ __align__(128) char smem[];
    __shared__ int sidx[128];
    const uint32_t sbase = smem_u32_of(smem);

    const int tid = threadIdx.x;
    const int wid = tid >> 5, lid = tid & 31;
    const int wm  = wid >> 2;
    const int wn  = wid & 3;
    const int m0  = blockIdx.y * 128;
    const int n0  = blockIdx.x * 128;

    if (GATHER) {
        const int cnt = __ldg(cnt_p);
        if (m0 >= cnt) return;
        if (tid < 128) sidx[tid] = __ldg(&idx[min(m0 + tid, cnt - 1)]);
        __syncthreads();
    }

    const int lrow = tid >> 2;
    const int lch  = tid & 3;

    const int ar0 = GATHER ? sidx[lrow]      : (m0 + lrow);
    const int ar1 = GATHER ? sidx[lrow + 64] : (m0 + lrow + 64);
    const size_t aoff0 = (size_t)ar0 * DIM;
    const size_t aoff1 = (size_t)ar1 * DIM;
    const size_t boff0 = (size_t)(n0 + lrow) * DIM;
    const size_t boff1 = (size_t)(n0 + lrow + 64) * DIM;

    auto load_stage = [&](int kt, int buf) {
        const size_t kofs = (size_t)kt * 32 + lch * 8;
        const uint32_t s0 = sbase + buf * STAGE;
        const uint32_t s1 = s0 + 8192;
        const uint32_t s2 = s0 + 16384;
        const uint32_t s3 = s0 + 24576;
        const uint32_t o0 = swz((uint32_t)lrow * 64 + lch * 16);
        const uint32_t o1 = swz((uint32_t)(lrow + 64) * 64 + lch * 16);
        cp16(s0 + o0, Ah + aoff0 + kofs);
        cp16(s0 + o1, Ah + aoff1 + kofs);
        cp16(s1 + o0, Am + aoff0 + kofs);
        cp16(s1 + o1, Am + aoff1 + kofs);
        cp16(s2 + o0, Bh + boff0 + kofs);
        cp16(s2 + o1, Bh + boff1 + kofs);
        cp16(s3 + o0, Bm + boff0 + kofs);
        cp16(s3 + o1, Bm + boff1 + kofs);
        asm volatile("cp.async.commit_group;" ::: "memory");
    };

    float acc[4][4][4];
#pragma unroll
    for (int i = 0; i < 4; i++)
#pragma unroll
        for (int j = 0; j < 4; j++)
#pragma unroll
            for (int r = 0; r < 4; r++) acc[i][j][r] = 0.f;

    const uint32_t a_row = wm * 64 + (lid & 7) + ((lid >> 3) & 1) * 8;
    const uint32_t a_kb  = ((lid >> 4) & 1) * 16;
    const uint32_t b_row = wn * 32 + (lid & 7) + ((lid >> 4) & 1) * 8;
    const uint32_t b_kb  = ((lid >> 3) & 1) * 16;

#pragma unroll
    for (int s = 0; s < NSF - 1; s++) load_stage(s, s);

    int buf = 0, nbuf = NSF - 1;
    for (int t = 0; t < KT; t++) {
        asm volatile("cp.async.wait_group %0;" :: "n"(NSF - 2) : "memory");
        __syncthreads();

        const uint32_t sAh = sbase + buf * STAGE;
        const uint32_t sAm = sAh + 8192;
        const uint32_t sBh = sAh + 16384;
        const uint32_t sBm = sAh + 24576;

#pragma unroll
        for (int ks = 0; ks < 2; ks++) {
            uint32_t bh[2][4], bm[2][4];
#pragma unroll
            for (int ng = 0; ng < 2; ng++) {
                ldsm_x4(bh[ng], sBh + swz((b_row + ng * 16) * 64 + ks * 32 + b_kb));
                ldsm_x4(bm[ng], sBm + swz((b_row + ng * 16) * 64 + ks * 32 + b_kb));
            }
#pragma unroll
            for (int mf = 0; mf < 4; mf++) {
                uint32_t a[4];
                ldsm_x4(a, sAh + swz((a_row + mf * 16) * 64 + ks * 32 + a_kb));
#pragma unroll
                for (int nf = 0; nf < 4; nf++)
                    mma16816(acc[mf][nf], a,
                             bh[nf >> 1][(nf & 1) * 2], bh[nf >> 1][(nf & 1) * 2 + 1]);
#pragma unroll
                for (int nf = 0; nf < 4; nf++)
                    mma16816(acc[mf][nf], a,
                             bm[nf >> 1][(nf & 1) * 2], bm[nf >> 1][(nf & 1) * 2 + 1]);
            }
#pragma unroll
            for (int mf = 0; mf < 4; mf++) {
                uint32_t a[4];
                ldsm_x4(a, sAm + swz((a_row + mf * 16) * 64 + ks * 32 + a_kb));
#pragma unroll
                for (int nf = 0; nf < 4; nf++)
                    mma16816(acc[mf][nf], a,
                             bh[nf >> 1][(nf & 1) * 2], bh[nf >> 1][(nf & 1) * 2 + 1]);
            }
        }

        if (t + NSF - 1 < KT) load_stage(t + NSF - 1, nbuf);
        if (++buf == NSF) buf = 0;
        if (++nbuf == NSF) nbuf = 0;
    }

    const int er = lid >> 2;
    const int ec = (lid & 3) * 2;
#pragma unroll
    for (int mf = 0; mf < 4; mf++) {
#pragma unroll
        for (int nf = 0; nf < 4; nf++) {
            const int col = n0 + wn * 32 + nf * 8 + ec;
            const float bx = __ldg(&bias[col]);
            const float by = __ldg(&bias[col + 1]);
            const int r0 = m0 + wm * 64 + mf * 16 + er;
            const int r1 = r0 + 8;
            *(float2*)(C + (size_t)r0 * DIM + col) = make_float2(acc[mf][nf][0] + bx, acc[mf][nf][1] + by);
            *(float2*)(C + (size_t)r1 * DIM + col) = make_float2(acc[mf][nf][2] + bx, acc[mf][nf][3] + by);
        }
    }
}

// ---------------------------------------------------------------------------
// fp32 -> 2-way bf16 split
// ---------------------------------------------------------------------------
__global__ __launch_bounds__(256)
void split2_kernel(const float* __restrict__ in, __nv_bfloat16* __restrict__ h,
                   __nv_bfloat16* __restrict__ m, size_t n)
{
    size_t i = ((size_t)blockIdx.x * 256 + threadIdx.x) * 4;
    if (i >= n) return;
    float4 v = *(const float4*)(in + i);
    float vv[4] = {v.x, v.y, v.z, v.w};
    __nv_bfloat16 hh[4], mm[4];
#pragma unroll
    for (int j = 0; j < 4; j++) {
        float x = vv[j];
        __nv_bfloat16 a = __float2bfloat16(x);
        float r = x - __bfloat162float(a);
        mm[j] = __float2bfloat16(r);
        hh[j] = a;
    }
    *(__nv_bfloat162*)(h + i)     = __nv_bfloat162(hh[0], hh[1]);
    *(__nv_bfloat162*)(h + i + 2) = __nv_bfloat162(hh[2], hh[3]);
    *(__nv_bfloat162*)(m + i)     = __nv_bfloat162(mm[0], mm[1]);
    *(__nv_bfloat162*)(m + i + 2) = __nv_bfloat162(mm[2], mm[3]);
}

// ---------------------------------------------------------------------------
// block reduction of two floats (256 threads)
// ---------------------------------------------------------------------------
__device__ __forceinline__ float2 block_reduce2(float a, float b)
{
    __shared__ float sa[8], sb[8];
    __syncthreads();
    int lane = threadIdx.x & 31, wd = threadIdx.x >> 5;
#pragma unroll
    for (int o = 16; o; o >>= 1) {
        a += __shfl_down_sync(0xFFFFFFFFu, a, o);
        b += __shfl_down_sync(0xFFFFFFFFu, b, o);
    }
    if (lane == 0) { sa[wd] = a; sb[wd] = b; }
    __syncthreads();
    if (wd == 0) {
        a = (lane < 8) ? sa[lane] : 0.f;
        b = (lane < 8) ? sb[lane] : 0.f;
#pragma unroll
        for (int o = 4; o; o >>= 1) {
            a += __shfl_down_sync(0xFFFFFFFFu, a, o);
            b += __shfl_down_sync(0xFFFFFFFFu, b, o);
        }
        if (lane == 0) { sa[0] = a; sb[0] = b; }
    }
    __syncthreads();
    return make_float2(sa[0], sb[0]);
}

// ---------------------------------------------------------------------------
// LN + ReLU + head, 8 rows per block, params in registers, next-row prefetch.
// (R13-proven unpaired version, 64 regs.)
// ---------------------------------------------------------------------------
template<bool SCATTER>
__global__ __launch_bounds__(256)
void ln_head8(const float* __restrict__ H,
              const float* __restrict__ gamma, const float* __restrict__ beta,
              const float* __restrict__ W2, const float* __restrict__ b2,
              const int* __restrict__ idx, const int* __restrict__ cnt_p,
              float* __restrict__ out)
{
    const int base = blockIdx.x * 8;
    int cnt = BATCH;
    if (SCATTER) {
        cnt = __ldg(cnt_p);
        if (base >= cnt) return;
    }
    const int t = threadIdx.x;

    const float4* g4  = (const float4*)gamma;
    const float4* be4 = (const float4*)beta;
    const float4* w04 = (const float4*)W2;
    const float4* w14 = (const float4*)(W2 + DIM);

    const float4 ga = g4[t*2],  gb = g4[t*2+1];
    const float4 ba = be4[t*2], bb = be4[t*2+1];
    const float4 wa = w04[t*2], wb = w04[t*2+1];
    const float4 wc = w14[t*2], wd = w14[t*2+1];
    const float bias0 = __ldg(&b2[0]), bias1 = __ldg(&b2[1]);
    const float inv_d = 1.f / (float)DIM;

    int rr0 = SCATTER ? min(base, cnt - 1) : base;
    const float4* h4 = (const float4*)(H + (size_t)rr0 * DIM);
    float4 v0 = h4[t*2];
    float4 v1 = h4[t*2+1];

#pragma unroll 1
    for (int r = 0; r < 8; r++) {
        const int row  = base + r;
        const bool act = !SCATTER || (row < cnt);

        float s  = v0.x + v0.y + v0.z + v0.w + v1.x + v1.y + v1.z + v1.w;
        float ss = v0.x*v0.x + v0.y*v0.y + v0.z*v0.z + v0.w*v0.w
                 + v1.x*v1.x + v1.y*v1.y + v1.z*v1.z + v1.w*v1.w;

        float4 n0v, n1v;
        if (r < 7) {
            const int nrow = base + r + 1;
            const int nrr  = SCATTER ? min(nrow, cnt - 1) : nrow;
            const float4* nh4 = (const float4*)(H + (size_t)nrr * DIM);
            n0v = nh4[t*2];
            n1v = nh4[t*2+1];
        }

        float2 red = block_reduce2(s, ss);
        float mu   = red.x * inv_d;
        float var  = red.y * inv_d - mu * mu;
        float rinv = rsqrtf(var + 1e-5f);

        float l0 = 0.f, l1 = 0.f, h;
        h = fmaxf(fmaf((v0.x - mu)*rinv, ga.x, ba.x), 0.f); l0 += h*wa.x; l1 += h*wc.x;
        h = fmaxf(fmaf((v0.y - mu)*rinv, ga.y, ba.y), 0.f); l0 += h*wa.y; l1 += h*wc.y;
        h = fmaxf(fmaf((v0.z - mu)*rinv, ga.z, ba.z), 0.f); l0 += h*wa.z; l1 += h*wc.z;
        h = fmaxf(fmaf((v0.w - mu)*rinv, ga.w, ba.w), 0.f); l0 += h*wa.w; l1 += h*wc.w;
        h = fmaxf(fmaf((v1.x - mu)*rinv, gb.x, bb.x), 0.f); l0 += h*wb.x; l1 += h*wd.x;
        h = fmaxf(fmaf((v1.y - mu)*rinv, gb.y, bb.y), 0.f); l0 += h*wb.y; l1 += h*wd.y;
        h = fmaxf(fmaf((v1.z - mu)*rinv, gb.z, bb.z), 0.f); l0 += h*wb.z; l1 += h*wd.z;
        h = fmaxf(fmaf((v1.w - mu)*rinv, gb.w, bb.w), 0.f); l0 += h*wb.w; l1 += h*wd.w;

        float2 lr = block_reduce2(l0, l1);
        if (t == 0 && act) {
            if (SCATTER) {
                const int o = __ldg(&idx[row]);
                out[o*2]   = lr.x + bias0;
                out[o*2+1] = lr.y + bias1;
            } else {
                out[row*2]   = lr.x + bias0;
                out[row*2+1] = lr.y + bias1;
            }
        }
        v0 = n0v;
        v1 = n1v;
    }
}

// bf16-H version: identical structure to ln_head8<false>, only loads convert.
__global__ __launch_bounds__(256)
void ln_head8_bf(const __nv_bfloat16* __restrict__ Hb,
                 const float* __restrict__ gamma, const float* __restrict__ beta,
                 const float* __restrict__ W2, const float* __restrict__ b2,
                 float* __restrict__ out)
{
    const int base = blockIdx.x * 8;
    const int t = threadIdx.x;

    const float4* g4  = (const float4*)gamma;
    const float4* be4 = (const float4*)beta;
    const float4* w04 = (const float4*)W2;
    const float4* w14 = (const float4*)(W2 + DIM);

    const float4 ga = g4[t*2],  gb = g4[t*2+1];
    const float4 ba = be4[t*2], bb = be4[t*2+1];
    const float4 wa = w04[t*2], wb = w04[t*2+1];
    const float4 wc = w14[t*2], wd = w14[t*2+1];
    const float bias0 = __ldg(&b2[0]), bias1 = __ldg(&b2[1]);
    const float inv_d = 1.f / (float)DIM;

    auto loadrow = [&](int row, float4& v0, float4& v1) {
        uint4 u = *(const uint4*)(Hb + (size_t)row * DIM + t * 8);
        float2 p0 = __bfloat1622float2(*(__nv_bfloat162*)&u.x);
        float2 p1 = __bfloat1622float2(*(__nv_bfloat162*)&u.y);
        float2 p2 = __bfloat1622float2(*(__nv_bfloat162*)&u.z);
        float2 p3 = __bfloat1622float2(*(__nv_bfloat162*)&u.w);
        v0 = make_float4(p0.x, p0.y, p1.x, p1.y);
        v1 = make_float4(p2.x, p2.y, p3.x, p3.y);
    };

    float4 v0, v1;
    loadrow(base, v0, v1);

#pragma unroll 1
    for (int r = 0; r < 8; r++) {
        const int row = base + r;

        float s  = v0.x + v0.y + v0.z + v0.w + v1.x + v1.y + v1.z + v1.w;
        float ss = v0.x*v0.x + v0.y*v0.y + v0.z*v0.z + v0.w*v0.w
                 + v1.x*v1.x + v1.y*v1.y + v1.z*v1.z + v1.w*v1.w;

        float4 n0v, n1v;
        if (r < 7) loadrow(base + r + 1, n0v, n1v);

        float2 red = block_reduce2(s, ss);
        float mu   = red.x * inv_d;
        float var  = red.y * inv_d - mu * mu;
        float rinv = rsqrtf(var + 1e-5f);

        float l0 = 0.f, l1 = 0.f, h;
        h = fmaxf(fmaf((v0.x - mu)*rinv, ga.x, ba.x), 0.f); l0 += h*wa.x; l1 += h*wc.x;
        h = fmaxf(fmaf((v0.y - mu)*rinv, ga.y, ba.y), 0.f); l0 += h*wa.y; l1 += h*wc.y;
        h = fmaxf(fmaf((v0.z - mu)*rinv, ga.z, ba.z), 0.f); l0 += h*wa.z; l1 += h*wc.z;
        h = fmaxf(fmaf((v0.w - mu)*rinv, ga.w, ba.w), 0.f); l0 += h*wa.w; l1 += h*wc.w;
        h = fmaxf(fmaf((v1.x - mu)*rinv, gb.x, bb.x), 0.f); l0 += h*wb.x; l1 += h*wd.x;
        h = fmaxf(fmaf((v1.y - mu)*rinv, gb.y, bb.y), 0.f); l0 += h*wb.y; l1 += h*wd.y;
        h = fmaxf(fmaf((v1.z - mu)*rinv, gb.z, bb.z), 0.f); l0 += h*wb.z; l1 += h*wd.z;
        h = fmaxf(fmaf((v1.w - mu)*rinv, gb.w, bb.w), 0.f); l0 += h*wb.w; l1 += h*wd.w;

        float2 lr = block_reduce2(l0, l1);
        if (t == 0) {
            out[row*2]   = lr.x + bias0;
            out[row*2+1] = lr.y + bias1;
        }
        v0 = n0v;
        v1 = n1v;
    }
}

// ---------------------------------------------------------------------------
// Flag rows with |l0-l1| < thresh. Single block, ordered compaction.
// ---------------------------------------------------------------------------
__global__ __launch_bounds__(1024)
void flag_scan(const float* __restrict__ L0, float thresh, int cap,
               int* __restrict__ rlist, int* __restrict__ rcnt)
{
    __shared__ int sf[1024];
    const int t = threadIdx.x;
    uint32_t mask = 0;
    int c = 0;
#pragma unroll
    for (int j = 0; j < 32; j++) {
        const int b = t * 32 + j;
        float2 f = ((const float2*)L0)[b];
        const bool fl = fabsf(f.x - f.y) < thresh;
        mask |= (uint32_t)fl << j;
        c += fl;
    }
    sf[t] = c;
    __syncthreads();
    for (int off = 1; off < 1024; off <<= 1) {
        int v = (t >= off) ? sf[t - off] : 0;
        __syncthreads();
        sf[t] += v;
        __syncthreads();
    }
    int pos = sf[t] - c;
#pragma unroll
    for (int j = 0; j < 32; j++) {
        if ((mask >> j) & 1) {
            if (pos < cap) rlist[pos] = t * 32 + j;
            pos++;
        }
    }
    if (t == 1023) rcnt[0] = min(sf[1023], cap);
}

// ---------------------------------------------------------------------------
// Exact fp32 recompute of h = x@W1.T + b1 for flagged rows (column-parallel).
// ---------------------------------------------------------------------------
__global__ __launch_bounds__(256)
void refine_h(const float* __restrict__ x, const float* __restrict__ W1,
              const float* __restrict__ b1,
              const int* __restrict__ rlist, const int* __restrict__ rcnt,
              float* __restrict__ Hr)
{
    const int slot = blockIdx.y;
    if (slot >= __ldg(rcnt)) return;
    const int row = __ldg(&rlist[slot]);

    __shared__ float sx[DIM];
    const int tid = threadIdx.x, wid = tid >> 5, lane = tid & 31;
    for (int i = tid; i < DIM; i += 256) sx[i] = x[(size_t)row * DIM + i];
    __syncthreads();

    const int col0 = blockIdx.x * 64;
#pragma unroll 1
    for (int c = wid; c < 64; c += 8) {
        const int j = col0 + c;
        const float* wr = W1 + (size_t)j * DIM;
        float acc = 0.f;
#pragma unroll 8
        for (int k = lane; k < DIM; k += 32)
            acc = fmaf(sx[k], __ldg(&wr[k]), acc);
#pragma unroll
        for (int o = 16; o; o >>= 1) acc += __shfl_down_sync(0xFFFFFFFFu, acc, o);
        if (lane == 0) Hr[(size_t)slot * DIM + j] = acc + __ldg(&b1[j]);
    }
}

// LN + head from exact h; patch L[row]. One block per slot.
__global__ __launch_bounds__(256)
void refine_fix(const float* __restrict__ Hr,
                const float* __restrict__ gamma, const float* __restrict__ beta,
                const float* __restrict__ W2, const float* __restrict__ b2,
                const int* __restrict__ rlist, const int* __restrict__ rcnt,
                float* __restrict__ L)
{
    const int slot = blockIdx.x;
    if (slot >= __ldg(rcnt)) return;
    const int t = threadIdx.x;
    const float4* h4 = (const float4*)(Hr + (size_t)slot * DIM);
    float4 v0 = h4[t*2];
    float4 v1 = h4[t*2+1];

    float s  = v0.x+v0.y+v0.z+v0.w + v1.x+v1.y+v1.z+v1.w;
    float ss = v0.x*v0.x+v0.y*v0.y+v0.z*v0.z+v0.w*v0.w
             + v1.x*v1.x+v1.y*v1.y+v1.z*v1.z+v1.w*v1.w;
    float2 red = block_reduce2(s, ss);
    const float inv_d = 1.f / (float)DIM;
    float mu = red.x * inv_d, var = red.y * inv_d - mu * mu;
    float rinv = rsqrtf(var + 1e-5f);

    const float4* g4  = (const float4*)gamma;
    const float4* be4 = (const float4*)beta;
    const float4* w04 = (const float4*)W2;
    const float4* w14 = (const float4*)(W2 + DIM);

    float l0 = 0.f, l1 = 0.f;
#pragma unroll
    for (int q = 0; q < 2; q++) {
        float4 v  = q ? v1 : v0;
        float4 g  = g4[t*2+q], be = be4[t*2+q], wav = w04[t*2+q], wbv = w14[t*2+q];
        float h;
        h = fmaxf(fmaf((v.x - mu)*rinv, g.x, be.x), 0.f); l0 += h*wav.x; l1 += h*wbv.x;
        h = fmaxf(fmaf((v.y - mu)*rinv, g.y, be.y), 0.f); l0 += h*wav.y; l1 += h*wbv.y;
        h = fmaxf(fmaf((v.z - mu)*rinv, g.z, be.z), 0.f); l0 += h*wav.z; l1 += h*wbv.z;
        h = fmaxf(fmaf((v.w - mu)*rinv, g.w, be.w), 0.f); l0 += h*wav.w; l1 += h*wbv.w;
    }
    float2 lr = block_reduce2(l0, l1);
    if (t == 0) {
        const int row = __ldg(&rlist[slot]);
        L[row*2]   = lr.x + __ldg(&b2[0]);
        L[row*2+1] = lr.y + __ldg(&b2[1]);
    }
}

// ---------------------------------------------------------------------------
// Deterministic route compaction: 1 block, 1024 threads, 32 rows each.
// ---------------------------------------------------------------------------
__global__ __launch_bounds__(1024)
void route_scan(const float* __restrict__ L0, int* __restrict__ fake_idx,
                int* __restrict__ real_idx, int* __restrict__ cnts)
{
    __shared__ int sf[1024];
    const int t = threadIdx.x;
    uint32_t mask = 0;
    int c = 0;
#pragma unroll
    for (int j = 0; j < 32; j++) {
        const int b = t * 32 + j;
        float2 f = ((const float2*)L0)[b];
        const bool fake = (f.x >= f.y);
        mask |= (uint32_t)fake << j;
        c += fake;
    }
    sf[t] = c;
    __syncthreads();
    for (int off = 1; off < 1024; off <<= 1) {
        int v = (t >= off) ? sf[t - off] : 0;
        __syncthreads();
        sf[t] += v;
        __syncthreads();
    }
    const int total_fake = sf[1023];
    const int excl = sf[t] - c;
    int fpos = excl;
#pragma unroll
    for (int j = 0; j < 32; j++) {
        const int b = t * 32 + j;
        if ((mask >> j) & 1) {
            fake_idx[fpos++] = b;
        } else {
            const int fake_before = excl + __popc(mask & ((1u << j) - 1u));
            real_idx[b - fake_before] = b;
        }
    }
    if (t == 0) { cnts[0] = total_fake; cnts[1] = BATCH - total_fake; }
}

// ---------------------------------------------------------------------------
extern "C" void kernel_launch(void* const* d_in, const int* in_sizes, int n_in,
                              void* d_out, int out_size)
{
    (void)in_sizes; (void)n_in; (void)out_size;
    const float* x = (const float*)d_in[0];

    float *H = nullptr, *L = nullptr, *Hr = nullptr;
    __nv_bfloat16 *Hb = nullptr;
    __nv_bfloat16 *xs = nullptr, *ws = nullptr;
    int *idx = nullptr, *cnt = nullptr;
    int *rl1 = nullptr, *rc1 = nullptr, *rl2 = nullptr, *rc2 = nullptr;
    cudaGetSymbolAddress((void**)&H,   g_H);
    cudaGetSymbolAddress((void**)&Hb,  g_Hb);
    cudaGetSymbolAddress((void**)&L,   g_logits);
    cudaGetSymbolAddress((void**)&Hr,  g_Hr);
    cudaGetSymbolAddress((void**)&xs,  g_xs);
    cudaGetSymbolAddress((void**)&ws,  g_ws);
    cudaGetSymbolAddress((void**)&idx, g_idx);
    cudaGetSymbolAddress((void**)&cnt, g_cnt);
    cudaGetSymbolAddress((void**)&rl1, g_rlist1);
    cudaGetSymbolAddress((void**)&rc1, g_rcnt1);
    cudaGetSymbolAddress((void**)&rl2, g_rlist2);
    cudaGetSymbolAddress((void**)&rc2, g_rcnt2);

    const size_t XN = (size_t)BATCH * DIM;
    const size_t WN = (size_t)DIM * DIM;
    __nv_bfloat16 *xh = xs, *xm = xs + XN;
    __nv_bfloat16 *wh = ws, *wm = ws + WN;

    constexpr int SMEM1 = NSTG * 16384;   // 96 KB
    constexpr int SMEM3 = NSF  * 32768;   // 96 KB
    cudaFuncSetAttribute(gemm_mma1,        cudaFuncAttributeMaxDynamicSharedMemorySize, SMEM1);
    cudaFuncSetAttribute(gemm_mma3f<true>, cudaFuncAttributeMaxDynamicSharedMemorySize, SMEM3);

    split2_kernel<<<(int)(XN / 4 / 256), 256>>>(x, xh, xm, XN);

    dim3 grid(DIM / 128, BATCH / 128);        // (16, 256)
    dim3 grid_t1(DIM / 128, RCAP1 / 128);     // (16, 64)

    // ---- first (routing) branch: 1-product bf16-H GEMM + tiered refine ----
    {
        const float* W1 = (const float*)d_in[1];
        const float* b1 = (const float*)d_in[2];
        const float* lg = (const float*)d_in[3];
        const float* lb = (const float*)d_in[4];
        const float* W2 = (const float*)d_in[5];
        const float* b2 = (const float*)d_in[6];
        split2_kernel<<<(int)(WN / 4 / 256), 256>>>(W1, wh, wm, WN);

        // tier-0: 1-product GEMM, bf16 H (gap error sigma ~2.6e-3 incl. bf16-H)
        gemm_mma1<<<grid, 256, SMEM1>>>(xh, wh, b1, Hb);
        ln_head8_bf<<<BATCH / 8, 256>>>(Hb, lg, lb, W2, b2, L);

        // tier-1: |gap| < 2.6e-2 (~10 sigma) -> fused 3-product recompute, patch L
        flag_scan<<<1, 1024>>>(L, 2.6e-2f, RCAP1, rl1, rc1);
        gemm_mma3f<true><<<grid_t1, 256, SMEM3>>>(xh, xm, wh, wm, b1, H, rl1, rc1);
        ln_head8<true><<<RCAP1 / 8, 256>>>(H, lg, lb, W2, b2, rl1, rc1, L);

        // tier-2: |gap| < 1e-3 -> exact fp32 recompute, patch L
        flag_scan<<<1, 1024>>>(L, 1e-3f, RCAP2, rl2, rc2);
        refine_h<<<dim3(32, RCAP2), 256>>>(x, W1, b1, rl2, rc2, Hr);
        refine_fix<<<RCAP2, 256>>>(Hr, lg, lb, W2, b2, rl2, rc2, L);
    }

    route_scan<<<1, 1024>>>(L, idx, idx + BATCH, cnt);

    // ---- fake (route==0) and real branches: fused 3-product, gathered ----
    for (int br = 1; br < 3; br++) {
        const float* W1 = (const float*)d_in[1 + br * 6 + 0];
        const float* b1 = (const float*)d_in[1 + br * 6 + 1];
        const float* lg = (const float*)d_in[1 + br * 6 + 2];
        const float* lb = (const float*)d_in[1 + br * 6 + 3];
        const float* W2 = (const float*)d_in[1 + br * 6 + 4];
        const float* b2 = (const float*)d_in[1 + br * 6 + 5];

        split2_kernel<<<(int)(WN / 4 / 256), 256>>>(W1, wh, wm, WN);

        int* bidx = idx + (br - 1) * BATCH;
        int* bcnt = cnt + (br - 1);
        gemm_mma3f<true><<<grid, 256, SMEM3>>>(xh, xm, wh, wm, b1, H, bidx, bcnt);
        ln_head8<true><<<BATCH / 8, 256>>>(H, lg, lb, W2, b2, bidx, bcnt,
                                           (float*)d_out);
    }
}

// round 16
// speedup vs baseline: 1.0228x; 1.0228x over previous
#include <cuda_runtime.h>
#include <cuda_bf16.h>
#include <cstdint>

#define DIM   2048
#define BATCH 32768
#define RCAP1 8192
#define RCAP2 256
#define NSTG  6              // pipeline depth for 1-product kernel
#define NSF   3              // pipeline depth for fused 3-product kernel

// ---------------------------------------------------------------------------
// Device-global scratch
// ---------------------------------------------------------------------------
__device__ __align__(16) float g_H[(size_t)BATCH * DIM];
__device__ __align__(16) float g_logits[BATCH * 2];
__device__ __align__(16) __nv_bfloat16 g_xs[2][(size_t)BATCH * DIM];
__device__ __align__(16) __nv_bfloat16 g_ws[2][(size_t)DIM * DIM];
__device__ __align__(16) float g_Hr[(size_t)RCAP2 * DIM];
__device__ int g_idx[2][BATCH];
__device__ int g_cnt[2];
__device__ int g_rlist1[RCAP1];
__device__ int g_rcnt1[1];
__device__ int g_rlist2[RCAP2];
__device__ int g_rcnt2[1];

// ---------------------------------------------------------------------------
// helpers
// ---------------------------------------------------------------------------
__device__ __forceinline__ uint32_t smem_u32_of(const void* p) {
    uint32_t a;
    asm("{ .reg .u64 t; cvta.to.shared.u64 t, %1; cvt.u32.u64 %0, t; }" : "=r"(a) : "l"(p));
    return a;
}
__device__ __forceinline__ void cp16(uint32_t dst, const void* src) {
    asm volatile("cp.async.cg.shared.global [%0], [%1], 16;" :: "r"(dst), "l"(src));
}
__device__ __forceinline__ void ldsm_x4(uint32_t* r, uint32_t addr) {
    asm volatile("ldmatrix.sync.aligned.m8n8.x4.shared.b16 {%0,%1,%2,%3}, [%4];"
                 : "=r"(r[0]), "=r"(r[1]), "=r"(r[2]), "=r"(r[3]) : "r"(addr));
}
__device__ __forceinline__ void mma16816(float* c, const uint32_t* a,
                                         uint32_t b0, uint32_t b1) {
    asm volatile("mma.sync.aligned.m16n8k16.row.col.f32.bf16.bf16.f32 "
                 "{%0,%1,%2,%3}, {%4,%5,%6,%7}, {%8,%9}, {%0,%1,%2,%3};"
                 : "+f"(c[0]), "+f"(c[1]), "+f"(c[2]), "+f"(c[3])
                 : "r"(a[0]), "r"(a[1]), "r"(a[2]), "r"(a[3]), "r"(b0), "r"(b1));
}
__device__ __forceinline__ uint32_t swz(uint32_t off) {       // Swizzle<3,4,3>
    return off ^ (((off >> 7) & 7u) << 4);
}

// ---------------------------------------------------------------------------
// 1-product bf16 GEMM (tier-0 routing): C = A_hi @ B_hi^T + bias (fp32 out)
// R9-proven config: tile 128x128, 8 warps, NSTG-stage cp.async, 2 CTAs/SM.
// ---------------------------------------------------------------------------
__global__ __launch_bounds__(256)
void gemm_mma1(const __nv_bfloat16* __restrict__ Ah,
               const __nv_bfloat16* __restrict__ Bh,
               const float* __restrict__ bias, float* __restrict__ C)
{
    constexpr int KT    = DIM / 32;
    constexpr int STAGE = 16384;

    extern __shared__ __align__(128) char smem[];
    const uint32_t sbase = smem_u32_of(smem);

    const int tid = threadIdx.x;
    const int wid = tid >> 5, lid = tid & 31;
    const int wm  = wid >> 2;
    const int wn  = wid & 3;
    const int m0  = blockIdx.y * 128;
    const int n0  = blockIdx.x * 128;

    const int lrow = tid >> 2;
    const int lch  = tid & 3;

    const size_t aoff0 = (size_t)(m0 + lrow) * DIM;
    const size_t aoff1 = (size_t)(m0 + lrow + 64) * DIM;
    const size_t boff0 = (size_t)(n0 + lrow) * DIM;
    const size_t boff1 = (size_t)(n0 + lrow + 64) * DIM;

    auto load_stage = [&](int kt, int buf) {
        const size_t kofs = (size_t)kt * 32 + lch * 8;
        const uint32_t sa = sbase + buf * STAGE;
        const uint32_t sb = sa + 8192;
        cp16(sa + swz((uint32_t)lrow * 64 + lch * 16),        Ah + aoff0 + kofs);
        cp16(sa + swz((uint32_t)(lrow + 64) * 64 + lch * 16), Ah + aoff1 + kofs);
        cp16(sb + swz((uint32_t)lrow * 64 + lch * 16),        Bh + boff0 + kofs);
        cp16(sb + swz((uint32_t)(lrow + 64) * 64 + lch * 16), Bh + boff1 + kofs);
        asm volatile("cp.async.commit_group;" ::: "memory");
    };

    float acc[4][4][4];
#pragma unroll
    for (int i = 0; i < 4; i++)
#pragma unroll
        for (int j = 0; j < 4; j++)
#pragma unroll
            for (int r = 0; r < 4; r++) acc[i][j][r] = 0.f;

    const uint32_t a_row = wm * 64 + (lid & 7) + ((lid >> 3) & 1) * 8;
    const uint32_t a_kb  = ((lid >> 4) & 1) * 16;
    const uint32_t b_row = wn * 32 + (lid & 7) + ((lid >> 4) & 1) * 8;
    const uint32_t b_kb  = ((lid >> 3) & 1) * 16;

#pragma unroll
    for (int s = 0; s < NSTG - 1; s++) load_stage(s, s);

    int buf = 0, nbuf = NSTG - 1;
    for (int t = 0; t < KT; t++) {
        asm volatile("cp.async.wait_group %0;" :: "n"(NSTG - 2) : "memory");
        __syncthreads();

        const uint32_t sa = sbase + buf * STAGE;
        const uint32_t sb = sa + 8192;

#pragma unroll
        for (int ks = 0; ks < 2; ks++) {
            uint32_t af[4][4], bf[2][4];
#pragma unroll
            for (int mf = 0; mf < 4; mf++)
                ldsm_x4(af[mf], sa + swz((a_row + mf * 16) * 64 + ks * 32 + a_kb));
#pragma unroll
            for (int ng = 0; ng < 2; ng++)
                ldsm_x4(bf[ng], sb + swz((b_row + ng * 16) * 64 + ks * 32 + b_kb));
#pragma unroll
            for (int mf = 0; mf < 4; mf++)
#pragma unroll
                for (int nf = 0; nf < 4; nf++)
                    mma16816(acc[mf][nf], af[mf],
                             bf[nf >> 1][(nf & 1) * 2], bf[nf >> 1][(nf & 1) * 2 + 1]);
        }

        if (t + NSTG - 1 < KT) load_stage(t + NSTG - 1, nbuf);
        if (++buf == NSTG) buf = 0;
        if (++nbuf == NSTG) nbuf = 0;
    }

    const int er = lid >> 2;
    const int ec = (lid & 3) * 2;
#pragma unroll
    for (int mf = 0; mf < 4; mf++) {
#pragma unroll
        for (int nf = 0; nf < 4; nf++) {
            const int col = n0 + wn * 32 + nf * 8 + ec;
            const float bx = __ldg(&bias[col]);
            const float by = __ldg(&bias[col + 1]);
            const int r0 = m0 + wm * 64 + mf * 16 + er;
            const int r1 = r0 + 8;
            *(float2*)(C + (size_t)r0 * DIM + col) = make_float2(acc[mf][nf][0] + bx, acc[mf][nf][1] + by);
            *(float2*)(C + (size_t)r1 * DIM + col) = make_float2(acc[mf][nf][2] + bx, acc[mf][nf][3] + by);
        }
    }
}

// ---------------------------------------------------------------------------
// FUSED 3-product bf16 GEMM: per k-tile load A_hi/A_mid/B_hi/B_mid once,
// accumulate hh + hm + mh. Tile 128x128, 8 warps, NSF stages, 2 CTAs/SM.
// ---------------------------------------------------------------------------
template<bool GATHER>
__global__ __launch_bounds__(256, 2)
void gemm_mma3f(const __nv_bfloat16* __restrict__ Ah, const __nv_bfloat16* __restrict__ Am,
                const __nv_bfloat16* __restrict__ Bh, const __nv_bfloat16* __restrict__ Bm,
                const float* __restrict__ bias, float* __restrict__ C,
                const int* __restrict__ idx, const int* __restrict__ cnt_p)
{
    constexpr int KT    = DIM / 32;
    constexpr int STAGE = 32768;

    extern __shared__ __align__(128) char smem[];
    __shared__ int sidx[128];
    const uint32_t sbase = smem_u32_of(smem);

    const int tid = threadIdx.x;
    const int wid = tid >> 5, lid = tid & 31;
    const int wm  = wid >> 2;
    const int wn  = wid & 3;
    const int m0  = blockIdx.y * 128;
    const int n0  = blockIdx.x * 128;

    if (GATHER) {
        const int cnt = __ldg(cnt_p);
        if (m0 >= cnt) return;
        if (tid < 128) sidx[tid] = __ldg(&idx[min(m0 + tid, cnt - 1)]);
        __syncthreads();
    }

    const int lrow = tid >> 2;
    const int lch  = tid & 3;

    const int ar0 = GATHER ? sidx[lrow]      : (m0 + lrow);
    const int ar1 = GATHER ? sidx[lrow + 64] : (m0 + lrow + 64);
    const size_t aoff0 = (size_t)ar0 * DIM;
    const size_t aoff1 = (size_t)ar1 * DIM;
    const size_t boff0 = (size_t)(n0 + lrow) * DIM;
    const size_t boff1 = (size_t)(n0 + lrow + 64) * DIM;

    auto load_stage = [&](int kt, int buf) {
        const size_t kofs = (size_t)kt * 32 + lch * 8;
        const uint32_t s0 = sbase + buf * STAGE;
        const uint32_t s1 = s0 + 8192;
        const uint32_t s2 = s0 + 16384;
        const uint32_t s3 = s0 + 24576;
        const uint32_t o0 = swz((uint32_t)lrow * 64 + lch * 16);
        const uint32_t o1 = swz((uint32_t)(lrow + 64) * 64 + lch * 16);
        cp16(s0 + o0, Ah + aoff0 + kofs);
        cp16(s0 + o1, Ah + aoff1 + kofs);
        cp16(s1 + o0, Am + aoff0 + kofs);
        cp16(s1 + o1, Am + aoff1 + kofs);
        cp16(s2 + o0, Bh + boff0 + kofs);
        cp16(s2 + o1, Bh + boff1 + kofs);
        cp16(s3 + o0, Bm + boff0 + kofs);
        cp16(s3 + o1, Bm + boff1 + kofs);
        asm volatile("cp.async.commit_group;" ::: "memory");
    };

    float acc[4][4][4];
#pragma unroll
    for (int i = 0; i < 4; i++)
#pragma unroll
        for (int j = 0; j < 4; j++)
#pragma unroll
            for (int r = 0; r < 4; r++) acc[i][j][r] = 0.f;

    const uint32_t a_row = wm * 64 + (lid & 7) + ((lid >> 3) & 1) * 8;
    const uint32_t a_kb  = ((lid >> 4) & 1) * 16;
    const uint32_t b_row = wn * 32 + (lid & 7) + ((lid >> 4) & 1) * 8;
    const uint32_t b_kb  = ((lid >> 3) & 1) * 16;

#pragma unroll
    for (int s = 0; s < NSF - 1; s++) load_stage(s, s);

    int buf = 0, nbuf = NSF - 1;
    for (int t = 0; t < KT; t++) {
        asm volatile("cp.async.wait_group %0;" :: "n"(NSF - 2) : "memory");
        __syncthreads();

        const uint32_t sAh = sbase + buf * STAGE;
        const uint32_t sAm = sAh + 8192;
        const uint32_t sBh = sAh + 16384;
        const uint32_t sBm = sAh + 24576;

#pragma unroll
        for (int ks = 0; ks < 2; ks++) {
            uint32_t bh[2][4], bm[2][4];
#pragma unroll
            for (int ng = 0; ng < 2; ng++) {
                ldsm_x4(bh[ng], sBh + swz((b_row + ng * 16) * 64 + ks * 32 + b_kb));
                ldsm_x4(bm[ng], sBm + swz((b_row + ng * 16) * 64 + ks * 32 + b_kb));
            }
#pragma unroll
            for (int mf = 0; mf < 4; mf++) {
                uint32_t a[4];
                ldsm_x4(a, sAh + swz((a_row + mf * 16) * 64 + ks * 32 + a_kb));
#pragma unroll
                for (int nf = 0; nf < 4; nf++)
                    mma16816(acc[mf][nf], a,
                             bh[nf >> 1][(nf & 1) * 2], bh[nf >> 1][(nf & 1) * 2 + 1]);
#pragma unroll
                for (int nf = 0; nf < 4; nf++)
                    mma16816(acc[mf][nf], a,
                             bm[nf >> 1][(nf & 1) * 2], bm[nf >> 1][(nf & 1) * 2 + 1]);
            }
#pragma unroll
            for (int mf = 0; mf < 4; mf++) {
                uint32_t a[4];
                ldsm_x4(a, sAm + swz((a_row + mf * 16) * 64 + ks * 32 + a_kb));
#pragma unroll
                for (int nf = 0; nf < 4; nf++)
                    mma16816(acc[mf][nf], a,
                             bh[nf >> 1][(nf & 1) * 2], bh[nf >> 1][(nf & 1) * 2 + 1]);
            }
        }

        if (t + NSF - 1 < KT) load_stage(t + NSF - 1, nbuf);
        if (++buf == NSF) buf = 0;
        if (++nbuf == NSF) nbuf = 0;
    }

    const int er = lid >> 2;
    const int ec = (lid & 3) * 2;
#pragma unroll
    for (int mf = 0; mf < 4; mf++) {
#pragma unroll
        for (int nf = 0; nf < 4; nf++) {
            const int col = n0 + wn * 32 + nf * 8 + ec;
            const float bx = __ldg(&bias[col]);
            const float by = __ldg(&bias[col + 1]);
            const int r0 = m0 + wm * 64 + mf * 16 + er;
            const int r1 = r0 + 8;
            *(float2*)(C + (size_t)r0 * DIM + col) = make_float2(acc[mf][nf][0] + bx, acc[mf][nf][1] + by);
            *(float2*)(C + (size_t)r1 * DIM + col) = make_float2(acc[mf][nf][2] + bx, acc[mf][nf][3] + by);
        }
    }
}

// ---------------------------------------------------------------------------
// fp32 -> 2-way bf16 split
// ---------------------------------------------------------------------------
__global__ __launch_bounds__(256)
void split2_kernel(const float* __restrict__ in, __nv_bfloat16* __restrict__ h,
                   __nv_bfloat16* __restrict__ m, size_t n)
{
    size_t i = ((size_t)blockIdx.x * 256 + threadIdx.x) * 4;
    if (i >= n) return;
    float4 v = *(const float4*)(in + i);
    float vv[4] = {v.x, v.y, v.z, v.w};
    __nv_bfloat16 hh[4], mm[4];
#pragma unroll
    for (int j = 0; j < 4; j++) {
        float x = vv[j];
        __nv_bfloat16 a = __float2bfloat16(x);
        float r = x - __bfloat162float(a);
        mm[j] = __float2bfloat16(r);
        hh[j] = a;
    }
    *(__nv_bfloat162*)(h + i)     = __nv_bfloat162(hh[0], hh[1]);
    *(__nv_bfloat162*)(h + i + 2) = __nv_bfloat162(hh[2], hh[3]);
    *(__nv_bfloat162*)(m + i)     = __nv_bfloat162(mm[0], mm[1]);
    *(__nv_bfloat162*)(m + i + 2) = __nv_bfloat162(mm[2], mm[3]);
}

// ---------------------------------------------------------------------------
// block reduction of two floats (256 threads)
// ---------------------------------------------------------------------------
__device__ __forceinline__ float2 block_reduce2(float a, float b)
{
    __shared__ float sa[8], sb[8];
    __syncthreads();
    int lane = threadIdx.x & 31, wd = threadIdx.x >> 5;
#pragma unroll
    for (int o = 16; o; o >>= 1) {
        a += __shfl_down_sync(0xFFFFFFFFu, a, o);
        b += __shfl_down_sync(0xFFFFFFFFu, b, o);
    }
    if (lane == 0) { sa[wd] = a; sb[wd] = b; }
    __syncthreads();
    if (wd == 0) {
        a = (lane < 8) ? sa[lane] : 0.f;
        b = (lane < 8) ? sb[lane] : 0.f;
#pragma unroll
        for (int o = 4; o; o >>= 1) {
            a += __shfl_down_sync(0xFFFFFFFFu, a, o);
            b += __shfl_down_sync(0xFFFFFFFFu, b, o);
        }
        if (lane == 0) { sa[0] = a; sb[0] = b; }
    }
    __syncthreads();
    return make_float2(sa[0], sb[0]);
}

// ---------------------------------------------------------------------------
// LN + ReLU + head, 8 rows per block, params in registers, next-row prefetch.
// ---------------------------------------------------------------------------
template<bool SCATTER>
__global__ __launch_bounds__(256)
void ln_head8(const float* __restrict__ H,
              const float* __restrict__ gamma, const float* __restrict__ beta,
              const float* __restrict__ W2, const float* __restrict__ b2,
              const int* __restrict__ idx, const int* __restrict__ cnt_p,
              float* __restrict__ out)
{
    const int base = blockIdx.x * 8;
    int cnt = BATCH;
    if (SCATTER) {
        cnt = __ldg(cnt_p);
        if (base >= cnt) return;
    }
    const int t = threadIdx.x;

    const float4* g4  = (const float4*)gamma;
    const float4* be4 = (const float4*)beta;
    const float4* w04 = (const float4*)W2;
    const float4* w14 = (const float4*)(W2 + DIM);

    const float4 ga = g4[t*2],  gb = g4[t*2+1];
    const float4 ba = be4[t*2], bb = be4[t*2+1];
    const float4 wa = w04[t*2], wb = w04[t*2+1];
    const float4 wc = w14[t*2], wd = w14[t*2+1];
    const float bias0 = __ldg(&b2[0]), bias1 = __ldg(&b2[1]);
    const float inv_d = 1.f / (float)DIM;

    int rr0 = SCATTER ? min(base, cnt - 1) : base;
    const float4* h4 = (const float4*)(H + (size_t)rr0 * DIM);
    float4 v0 = h4[t*2];
    float4 v1 = h4[t*2+1];

#pragma unroll 1
    for (int r = 0; r < 8; r++) {
        const int row  = base + r;
        const bool act = !SCATTER || (row < cnt);

        float s  = v0.x + v0.y + v0.z + v0.w + v1.x + v1.y + v1.z + v1.w;
        float ss = v0.x*v0.x + v0.y*v0.y + v0.z*v0.z + v0.w*v0.w
                 + v1.x*v1.x + v1.y*v1.y + v1.z*v1.z + v1.w*v1.w;

        float4 n0v, n1v;
        if (r < 7) {
            const int nrow = base + r + 1;
            const int nrr  = SCATTER ? min(nrow, cnt - 1) : nrow;
            const float4* nh4 = (const float4*)(H + (size_t)nrr * DIM);
            n0v = nh4[t*2];
            n1v = nh4[t*2+1];
        }

        float2 red = block_reduce2(s, ss);
        float mu   = red.x * inv_d;
        float var  = red.y * inv_d - mu * mu;
        float rinv = rsqrtf(var + 1e-5f);

        float l0 = 0.f, l1 = 0.f, h;
        h = fmaxf(fmaf((v0.x - mu)*rinv, ga.x, ba.x), 0.f); l0 += h*wa.x; l1 += h*wc.x;
        h = fmaxf(fmaf((v0.y - mu)*rinv, ga.y, ba.y), 0.f); l0 += h*wa.y; l1 += h*wc.y;
        h = fmaxf(fmaf((v0.z - mu)*rinv, ga.z, ba.z), 0.f); l0 += h*wa.z; l1 += h*wc.z;
        h = fmaxf(fmaf((v0.w - mu)*rinv, ga.w, ba.w), 0.f); l0 += h*wa.w; l1 += h*wc.w;
        h = fmaxf(fmaf((v1.x - mu)*rinv, gb.x, bb.x), 0.f); l0 += h*wb.x; l1 += h*wd.x;
        h = fmaxf(fmaf((v1.y - mu)*rinv, gb.y, bb.y), 0.f); l0 += h*wb.y; l1 += h*wd.y;
        h = fmaxf(fmaf((v1.z - mu)*rinv, gb.z, bb.z), 0.f); l0 += h*wb.z; l1 += h*wd.z;
        h = fmaxf(fmaf((v1.w - mu)*rinv, gb.w, bb.w), 0.f); l0 += h*wb.w; l1 += h*wd.w;

        float2 lr = block_reduce2(l0, l1);
        if (t == 0 && act) {
            if (SCATTER) {
                const int o = __ldg(&idx[row]);
                out[o*2]   = lr.x + bias0;
                out[o*2+1] = lr.y + bias1;
            } else {
                out[row*2]   = lr.x + bias0;
                out[row*2+1] = lr.y + bias1;
            }
        }
        v0 = n0v;
        v1 = n1v;
    }
}

// ---------------------------------------------------------------------------
// Flag rows with |l0-l1| < thresh. Single block, ordered compaction.
// ---------------------------------------------------------------------------
__global__ __launch_bounds__(1024)
void flag_scan(const float* __restrict__ L0, float thresh, int cap,
               int* __restrict__ rlist, int* __restrict__ rcnt)
{
    __shared__ int sf[1024];
    const int t = threadIdx.x;
    uint32_t mask = 0;
    int c = 0;
#pragma unroll
    for (int j = 0; j < 32; j++) {
        const int b = t * 32 + j;
        float2 f = ((const float2*)L0)[b];
        const bool fl = fabsf(f.x - f.y) < thresh;
        mask |= (uint32_t)fl << j;
        c += fl;
    }
    sf[t] = c;
    __syncthreads();
    for (int off = 1; off < 1024; off <<= 1) {
        int v = (t >= off) ? sf[t - off] : 0;
        __syncthreads();
        sf[t] += v;
        __syncthreads();
    }
    int pos = sf[t] - c;
#pragma unroll
    for (int j = 0; j < 32; j++) {
        if ((mask >> j) & 1) {
            if (pos < cap) rlist[pos] = t * 32 + j;
            pos++;
        }
    }
    if (t == 1023) rcnt[0] = min(sf[1023], cap);
}

// ---------------------------------------------------------------------------
// Exact fp32 recompute of h = x@W1.T + b1 for flagged rows (column-parallel).
// ---------------------------------------------------------------------------
__global__ __launch_bounds__(256)
void refine_h(const float* __restrict__ x, const float* __restrict__ W1,
              const float* __restrict__ b1,
              const int* __restrict__ rlist, const int* __restrict__ rcnt,
              float* __restrict__ Hr)
{
    const int slot = blockIdx.y;
    if (slot >= __ldg(rcnt)) return;
    const int row = __ldg(&rlist[slot]);

    __shared__ float sx[DIM];
    const int tid = threadIdx.x, wid = tid >> 5, lane = tid & 31;
    for (int i = tid; i < DIM; i += 256) sx[i] = x[(size_t)row * DIM + i];
    __syncthreads();

    const int col0 = blockIdx.x * 64;
#pragma unroll 1
    for (int c = wid; c < 64; c += 8) {
        const int j = col0 + c;
        const float* wr = W1 + (size_t)j * DIM;
        float acc = 0.f;
#pragma unroll 8
        for (int k = lane; k < DIM; k += 32)
            acc = fmaf(sx[k], __ldg(&wr[k]), acc);
#pragma unroll
        for (int o = 16; o; o >>= 1) acc += __shfl_down_sync(0xFFFFFFFFu, acc, o);
        if (lane == 0) Hr[(size_t)slot * DIM + j] = acc + __ldg(&b1[j]);
    }
}

// LN + head from exact h; patch L[row]. One block per slot.
__global__ __launch_bounds__(256)
void refine_fix(const float* __restrict__ Hr,
                const float* __restrict__ gamma, const float* __restrict__ beta,
                const float* __restrict__ W2, const float* __restrict__ b2,
                const int* __restrict__ rlist, const int* __restrict__ rcnt,
                float* __restrict__ L)
{
    const int slot = blockIdx.x;
    if (slot >= __ldg(rcnt)) return;
    const int t = threadIdx.x;
    const float4* h4 = (const float4*)(Hr + (size_t)slot * DIM);
    float4 v0 = h4[t*2];
    float4 v1 = h4[t*2+1];

    float s  = v0.x+v0.y+v0.z+v0.w + v1.x+v1.y+v1.z+v1.w;
    float ss = v0.x*v0.x+v0.y*v0.y+v0.z*v0.z+v0.w*v0.w
             + v1.x*v1.x+v1.y*v1.y+v1.z*v1.z+v1.w*v1.w;
    float2 red = block_reduce2(s, ss);
    const float inv_d = 1.f / (float)DIM;
    float mu = red.x * inv_d, var = red.y * inv_d - mu * mu;
    float rinv = rsqrtf(var + 1e-5f);

    const float4* g4  = (const float4*)gamma;
    const float4* be4 = (const float4*)beta;
    const float4* w04 = (const float4*)W2;
    const float4* w14 = (const float4*)(W2 + DIM);

    float l0 = 0.f, l1 = 0.f;
#pragma unroll
    for (int q = 0; q < 2; q++) {
        float4 v  = q ? v1 : v0;
        float4 g  = g4[t*2+q], be = be4[t*2+q], wav = w04[t*2+q], wbv = w14[t*2+q];
        float h;
        h = fmaxf(fmaf((v.x - mu)*rinv, g.x, be.x), 0.f); l0 += h*wav.x; l1 += h*wbv.x;
        h = fmaxf(fmaf((v.y - mu)*rinv, g.y, be.y), 0.f); l0 += h*wav.y; l1 += h*wbv.y;
        h = fmaxf(fmaf((v.z - mu)*rinv, g.z, be.z), 0.f); l0 += h*wav.z; l1 += h*wbv.z;
        h = fmaxf(fmaf((v.w - mu)*rinv, g.w, be.w), 0.f); l0 += h*wav.w; l1 += h*wbv.w;
    }
    float2 lr = block_reduce2(l0, l1);
    if (t == 0) {
        const int row = __ldg(&rlist[slot]);
        L[row*2]   = lr.x + __ldg(&b2[0]);
        L[row*2+1] = lr.y + __ldg(&b2[1]);
    }
}

// ---------------------------------------------------------------------------
// Deterministic route compaction: 1 block, 1024 threads, 32 rows each.
// ---------------------------------------------------------------------------
__global__ __launch_bounds__(1024)
void route_scan(const float* __restrict__ L0, int* __restrict__ fake_idx,
                int* __restrict__ real_idx, int* __restrict__ cnts)
{
    __shared__ int sf[1024];
    const int t = threadIdx.x;
    uint32_t mask = 0;
    int c = 0;
#pragma unroll
    for (int j = 0; j < 32; j++) {
        const int b = t * 32 + j;
        float2 f = ((const float2*)L0)[b];
        const bool fake = (f.x >= f.y);
        mask |= (uint32_t)fake << j;
        c += fake;
    }
    sf[t] = c;
    __syncthreads();
    for (int off = 1; off < 1024; off <<= 1) {
        int v = (t >= off) ? sf[t - off] : 0;
        __syncthreads();
        sf[t] += v;
        __syncthreads();
    }
    const int total_fake = sf[1023];
    const int excl = sf[t] - c;
    int fpos = excl;
#pragma unroll
    for (int j = 0; j < 32; j++) {
        const int b = t * 32 + j;
        if ((mask >> j) & 1) {
            fake_idx[fpos++] = b;
        } else {
            const int fake_before = excl + __popc(mask & ((1u << j) - 1u));
            real_idx[b - fake_before] = b;
        }
    }
    if (t == 0) { cnts[0] = total_fake; cnts[1] = BATCH - total_fake; }
}

// ---------------------------------------------------------------------------
extern "C" void kernel_launch(void* const* d_in, const int* in_sizes, int n_in,
                              void* d_out, int out_size)
{
    (void)in_sizes; (void)n_in; (void)out_size;
    const float* x = (const float*)d_in[0];

    float *H = nullptr, *L = nullptr, *Hr = nullptr;
    __nv_bfloat16 *xs = nullptr, *ws = nullptr;
    int *idx = nullptr, *cnt = nullptr;
    int *rl1 = nullptr, *rc1 = nullptr, *rl2 = nullptr, *rc2 = nullptr;
    cudaGetSymbolAddress((void**)&H,   g_H);
    cudaGetSymbolAddress((void**)&L,   g_logits);
    cudaGetSymbolAddress((void**)&Hr,  g_Hr);
    cudaGetSymbolAddress((void**)&xs,  g_xs);
    cudaGetSymbolAddress((void**)&ws,  g_ws);
    cudaGetSymbolAddress((void**)&idx, g_idx);
    cudaGetSymbolAddress((void**)&cnt, g_cnt);
    cudaGetSymbolAddress((void**)&rl1, g_rlist1);
    cudaGetSymbolAddress((void**)&rc1, g_rcnt1);
    cudaGetSymbolAddress((void**)&rl2, g_rlist2);
    cudaGetSymbolAddress((void**)&rc2, g_rcnt2);

    const size_t XN = (size_t)BATCH * DIM;
    const size_t WN = (size_t)DIM * DIM;
    __nv_bfloat16 *xh = xs, *xm = xs + XN;
    __nv_bfloat16 *wh = ws, *wm = ws + WN;

    constexpr int SMEM1 = NSTG * 16384;   // 96 KB
    constexpr int SMEM3 = NSF  * 32768;   // 96 KB
    cudaFuncSetAttribute(gemm_mma1,        cudaFuncAttributeMaxDynamicSharedMemorySize, SMEM1);
    cudaFuncSetAttribute(gemm_mma3f<true>, cudaFuncAttributeMaxDynamicSharedMemorySize, SMEM3);

    split2_kernel<<<(int)(XN / 4 / 256), 256>>>(x, xh, xm, XN);

    dim3 grid(DIM / 128, BATCH / 128);        // (16, 256)
    dim3 grid_t1(DIM / 128, RCAP1 / 128);     // (16, 64)

    // ---- first (routing) branch: 1-product GEMM + tiered refine ----
    {
        const float* W1 = (const float*)d_in[1];
        const float* b1 = (const float*)d_in[2];
        const float* lg = (const float*)d_in[3];
        const float* lb = (const float*)d_in[4];
        const float* W2 = (const float*)d_in[5];
        const float* b2 = (const float*)d_in[6];
        split2_kernel<<<(int)(WN / 4 / 256), 256>>>(W1, wh, wm, WN);

        // tier-0: 1-product (hi*hi) full-batch GEMM (gap error sigma ~2.3e-3)
        gemm_mma1<<<grid, 256, SMEM1>>>(xh, wh, b1, H);
        ln_head8<false><<<BATCH / 8, 256>>>(H, lg, lb, W2, b2, nullptr, nullptr, L);

        // tier-1: |gap| < 2e-2 (~8.7 sigma) -> fused 3-product recompute, patch L
        flag_scan<<<1, 1024>>>(L, 2e-2f, RCAP1, rl1, rc1);
        gemm_mma3f<true><<<grid_t1, 256, SMEM3>>>(xh, xm, wh, wm, b1, H, rl1, rc1);
        ln_head8<true><<<RCAP1 / 8, 256>>>(H, lg, lb, W2, b2, rl1, rc1, L);

        // tier-2: |gap| < 1e-3 -> exact fp32 recompute, patch L
        flag_scan<<<1, 1024>>>(L, 1e-3f, RCAP2, rl2, rc2);
        refine_h<<<dim3(32, RCAP2), 256>>>(x, W1, b1, rl2, rc2, Hr);
        refine_fix<<<RCAP2, 256>>>(Hr, lg, lb, W2, b2, rl2, rc2, L);
    }

    route_scan<<<1, 1024>>>(L, idx, idx + BATCH, cnt);

    // ---- fake (route==0) and real branches: fused 3-product, gathered ----
    for (int br = 1; br < 3; br++) {
        const float* W1 = (const float*)d_in[1 + br * 6 + 0];
        const float* b1 = (const float*)d_in[1 + br * 6 + 1];
        const float* lg = (const float*)d_in[1 + br * 6 + 2];
        const float* lb = (const float*)d_in[1 + br * 6 + 3];
        const float* W2 = (const float*)d_in[1 + br * 6 + 4];
        const float* b2 = (const float*)d_in[1 + br * 6 + 5];

        split2_kernel<<<(int)(WN / 4 / 256), 256>>>(W1, wh, wm, WN);

        int* bidx = idx + (br - 1) * BATCH;
        int* bcnt = cnt + (br - 1);
        gemm_mma3f<true><<<grid, 256, SMEM3>>>(xh, xm, wh, wm, b1, H, bidx, bcnt);
        ln_head8<true><<<BATCH / 8, 256>>>(H, lg, lb, W2, b2, bidx, bcnt,
                                           (float*)d_out);
    }
}

// round 17
// speedup vs baseline: 1.0483x; 1.0249x over previous
#include <cuda_runtime.h>
#include <cuda_bf16.h>
#include <cstdint>

#define DIM   2048
#define BATCH 32768
#define RCAP1 8192
#define RCAP2 256
#define NSTG  6              // pipeline depth for 1-product kernel
#define NSF   3              // pipeline depth for fused 3-product kernel

// ---------------------------------------------------------------------------
// Device-global scratch
// ---------------------------------------------------------------------------
__device__ __align__(16) float g_H[(size_t)BATCH * DIM];                 // routing + fake
__device__ __align__(16) float g_H2[(size_t)BATCH * DIM];                // real branch
__device__ __align__(16) float g_logits[BATCH * 2];
__device__ __align__(16) __nv_bfloat16 g_xs[2][(size_t)BATCH * DIM];
__device__ __align__(16) __nv_bfloat16 g_ws[3][2][(size_t)DIM * DIM];    // per-branch W splits
__device__ __align__(16) float g_Hr[(size_t)RCAP2 * DIM];
__device__ int g_idx[2][BATCH];
__device__ int g_cnt[2];
__device__ int g_rlist1[RCAP1];
__device__ int g_rcnt1[1];
__device__ int g_rlist2[RCAP2];
__device__ int g_rcnt2[1];

// ---------------------------------------------------------------------------
// helpers
// ---------------------------------------------------------------------------
__device__ __forceinline__ uint32_t smem_u32_of(const void* p) {
    uint32_t a;
    asm("{ .reg .u64 t; cvta.to.shared.u64 t, %1; cvt.u32.u64 %0, t; }" : "=r"(a) : "l"(p));
    return a;
}
__device__ __forceinline__ void cp16(uint32_t dst, const void* src) {
    asm volatile("cp.async.cg.shared.global [%0], [%1], 16;" :: "r"(dst), "l"(src));
}
__device__ __forceinline__ void ldsm_x4(uint32_t* r, uint32_t addr) {
    asm volatile("ldmatrix.sync.aligned.m8n8.x4.shared.b16 {%0,%1,%2,%3}, [%4];"
                 : "=r"(r[0]), "=r"(r[1]), "=r"(r[2]), "=r"(r[3]) : "r"(addr));
}
__device__ __forceinline__ void mma16816(float* c, const uint32_t* a,
                                         uint32_t b0, uint32_t b1) {
    asm volatile("mma.sync.aligned.m16n8k16.row.col.f32.bf16.bf16.f32 "
                 "{%0,%1,%2,%3}, {%4,%5,%6,%7}, {%8,%9}, {%0,%1,%2,%3};"
                 : "+f"(c[0]), "+f"(c[1]), "+f"(c[2]), "+f"(c[3])
                 : "r"(a[0]), "r"(a[1]), "r"(a[2]), "r"(a[3]), "r"(b0), "r"(b1));
}
__device__ __forceinline__ uint32_t swz(uint32_t off) {       // Swizzle<3,4,3>
    return off ^ (((off >> 7) & 7u) << 4);
}

// ---------------------------------------------------------------------------
// 1-product bf16 GEMM (tier-0 routing): C = A_hi @ B_hi^T + bias (fp32 out)
// ---------------------------------------------------------------------------
__global__ __launch_bounds__(256)
void gemm_mma1(const __nv_bfloat16* __restrict__ Ah,
               const __nv_bfloat16* __restrict__ Bh,
               const float* __restrict__ bias, float* __restrict__ C)
{
    constexpr int KT    = DIM / 32;
    constexpr int STAGE = 16384;

    extern __shared__ __align__(128) char smem[];
    const uint32_t sbase = smem_u32_of(smem);

    const int tid = threadIdx.x;
    const int wid = tid >> 5, lid = tid & 31;
    const int wm  = wid >> 2;
    const int wn  = wid & 3;
    const int m0  = blockIdx.y * 128;
    const int n0  = blockIdx.x * 128;

    const int lrow = tid >> 2;
    const int lch  = tid & 3;

    const size_t aoff0 = (size_t)(m0 + lrow) * DIM;
    const size_t aoff1 = (size_t)(m0 + lrow + 64) * DIM;
    const size_t boff0 = (size_t)(n0 + lrow) * DIM;
    const size_t boff1 = (size_t)(n0 + lrow + 64) * DIM;

    auto load_stage = [&](int kt, int buf) {
        const size_t kofs = (size_t)kt * 32 + lch * 8;
        const uint32_t sa = sbase + buf * STAGE;
        const uint32_t sb = sa + 8192;
        cp16(sa + swz((uint32_t)lrow * 64 + lch * 16),        Ah + aoff0 + kofs);
        cp16(sa + swz((uint32_t)(lrow + 64) * 64 + lch * 16), Ah + aoff1 + kofs);
        cp16(sb + swz((uint32_t)lrow * 64 + lch * 16),        Bh + boff0 + kofs);
        cp16(sb + swz((uint32_t)(lrow + 64) * 64 + lch * 16), Bh + boff1 + kofs);
        asm volatile("cp.async.commit_group;" ::: "memory");
    };

    float acc[4][4][4];
#pragma unroll
    for (int i = 0; i < 4; i++)
#pragma unroll
        for (int j = 0; j < 4; j++)
#pragma unroll
            for (int r = 0; r < 4; r++) acc[i][j][r] = 0.f;

    const uint32_t a_row = wm * 64 + (lid & 7) + ((lid >> 3) & 1) * 8;
    const uint32_t a_kb  = ((lid >> 4) & 1) * 16;
    const uint32_t b_row = wn * 32 + (lid & 7) + ((lid >> 4) & 1) * 8;
    const uint32_t b_kb  = ((lid >> 3) & 1) * 16;

#pragma unroll
    for (int s = 0; s < NSTG - 1; s++) load_stage(s, s);

    int buf = 0, nbuf = NSTG - 1;
    for (int t = 0; t < KT; t++) {
        asm volatile("cp.async.wait_group %0;" :: "n"(NSTG - 2) : "memory");
        __syncthreads();

        const uint32_t sa = sbase + buf * STAGE;
        const uint32_t sb = sa + 8192;

#pragma unroll
        for (int ks = 0; ks < 2; ks++) {
            uint32_t af[4][4], bf[2][4];
#pragma unroll
            for (int mf = 0; mf < 4; mf++)
                ldsm_x4(af[mf], sa + swz((a_row + mf * 16) * 64 + ks * 32 + a_kb));
#pragma unroll
            for (int ng = 0; ng < 2; ng++)
                ldsm_x4(bf[ng], sb + swz((b_row + ng * 16) * 64 + ks * 32 + b_kb));
#pragma unroll
            for (int mf = 0; mf < 4; mf++)
#pragma unroll
                for (int nf = 0; nf < 4; nf++)
                    mma16816(acc[mf][nf], af[mf],
                             bf[nf >> 1][(nf & 1) * 2], bf[nf >> 1][(nf & 1) * 2 + 1]);
        }

        if (t + NSTG - 1 < KT) load_stage(t + NSTG - 1, nbuf);
        if (++buf == NSTG) buf = 0;
        if (++nbuf == NSTG) nbuf = 0;
    }

    const int er = lid >> 2;
    const int ec = (lid & 3) * 2;
#pragma unroll
    for (int mf = 0; mf < 4; mf++) {
#pragma unroll
        for (int nf = 0; nf < 4; nf++) {
            const int col = n0 + wn * 32 + nf * 8 + ec;
            const float bx = __ldg(&bias[col]);
            const float by = __ldg(&bias[col + 1]);
            const int r0 = m0 + wm * 64 + mf * 16 + er;
            const int r1 = r0 + 8;
            *(float2*)(C + (size_t)r0 * DIM + col) = make_float2(acc[mf][nf][0] + bx, acc[mf][nf][1] + by);
            *(float2*)(C + (size_t)r1 * DIM + col) = make_float2(acc[mf][nf][2] + bx, acc[mf][nf][3] + by);
        }
    }
}

// ---------------------------------------------------------------------------
// FUSED 3-product bf16 GEMM: per k-tile load A_hi/A_mid/B_hi/B_mid once,
// accumulate hh + hm + mh. Tile 128x128, 8 warps, NSF stages, 2 CTAs/SM.
// ---------------------------------------------------------------------------
template<bool GATHER>
__global__ __launch_bounds__(256, 2)
void gemm_mma3f(const __nv_bfloat16* __restrict__ Ah, const __nv_bfloat16* __restrict__ Am,
                const __nv_bfloat16* __restrict__ Bh, const __nv_bfloat16* __restrict__ Bm,
                const float* __restrict__ bias, float* __restrict__ C,
                const int* __restrict__ idx, const int* __restrict__ cnt_p)
{
    constexpr int KT    = DIM / 32;
    constexpr int STAGE = 32768;

    extern __shared__ __align__(128) char smem[];
    __shared__ int sidx[128];
    const uint32_t sbase = smem_u32_of(smem);

    const int tid = threadIdx.x;
    const int wid = tid >> 5, lid = tid & 31;
    const int wm  = wid >> 2;
    const int wn  = wid & 3;
    const int m0  = blockIdx.y * 128;
    const int n0  = blockIdx.x * 128;

    if (GATHER) {
        const int cnt = __ldg(cnt_p);
        if (m0 >= cnt) return;
        if (tid < 128) sidx[tid] = __ldg(&idx[min(m0 + tid, cnt - 1)]);
        __syncthreads();
    }

    const int lrow = tid >> 2;
    const int lch  = tid & 3;

    const int ar0 = GATHER ? sidx[lrow]      : (m0 + lrow);
    const int ar1 = GATHER ? sidx[lrow + 64] : (m0 + lrow + 64);
    const size_t aoff0 = (size_t)ar0 * DIM;
    const size_t aoff1 = (size_t)ar1 * DIM;
    const size_t boff0 = (size_t)(n0 + lrow) * DIM;
    const size_t boff1 = (size_t)(n0 + lrow + 64) * DIM;

    auto load_stage = [&](int kt, int buf) {
        const size_t kofs = (size_t)kt * 32 + lch * 8;
        const uint32_t s0 = sbase + buf * STAGE;
        const uint32_t s1 = s0 + 8192;
        const uint32_t s2 = s0 + 16384;
        const uint32_t s3 = s0 + 24576;
        const uint32_t o0 = swz((uint32_t)lrow * 64 + lch * 16);
        const uint32_t o1 = swz((uint32_t)(lrow + 64) * 64 + lch * 16);
        cp16(s0 + o0, Ah + aoff0 + kofs);
        cp16(s0 + o1, Ah + aoff1 + kofs);
        cp16(s1 + o0, Am + aoff0 + kofs);
        cp16(s1 + o1, Am + aoff1 + kofs);
        cp16(s2 + o0, Bh + boff0 + kofs);
        cp16(s2 + o1, Bh + boff1 + kofs);
        cp16(s3 + o0, Bm + boff0 + kofs);
        cp16(s3 + o1, Bm + boff1 + kofs);
        asm volatile("cp.async.commit_group;" ::: "memory");
    };

    float acc[4][4][4];
#pragma unroll
    for (int i = 0; i < 4; i++)
#pragma unroll
        for (int j = 0; j < 4; j++)
#pragma unroll
            for (int r = 0; r < 4; r++) acc[i][j][r] = 0.f;

    const uint32_t a_row = wm * 64 + (lid & 7) + ((lid >> 3) & 1) * 8;
    const uint32_t a_kb  = ((lid >> 4) & 1) * 16;
    const uint32_t b_row = wn * 32 + (lid & 7) + ((lid >> 4) & 1) * 8;
    const uint32_t b_kb  = ((lid >> 3) & 1) * 16;

#pragma unroll
    for (int s = 0; s < NSF - 1; s++) load_stage(s, s);

    int buf = 0, nbuf = NSF - 1;
    for (int t = 0; t < KT; t++) {
        asm volatile("cp.async.wait_group %0;" :: "n"(NSF - 2) : "memory");
        __syncthreads();

        const uint32_t sAh = sbase + buf * STAGE;
        const uint32_t sAm = sAh + 8192;
        const uint32_t sBh = sAh + 16384;
        const uint32_t sBm = sAh + 24576;

#pragma unroll
        for (int ks = 0; ks < 2; ks++) {
            uint32_t bh[2][4], bm[2][4];
#pragma unroll
            for (int ng = 0; ng < 2; ng++) {
                ldsm_x4(bh[ng], sBh + swz((b_row + ng * 16) * 64 + ks * 32 + b_kb));
                ldsm_x4(bm[ng], sBm + swz((b_row + ng * 16) * 64 + ks * 32 + b_kb));
            }
#pragma unroll
            for (int mf = 0; mf < 4; mf++) {
                uint32_t a[4];
                ldsm_x4(a, sAh + swz((a_row + mf * 16) * 64 + ks * 32 + a_kb));
#pragma unroll
                for (int nf = 0; nf < 4; nf++)
                    mma16816(acc[mf][nf], a,
                             bh[nf >> 1][(nf & 1) * 2], bh[nf >> 1][(nf & 1) * 2 + 1]);
#pragma unroll
                for (int nf = 0; nf < 4; nf++)
                    mma16816(acc[mf][nf], a,
                             bm[nf >> 1][(nf & 1) * 2], bm[nf >> 1][(nf & 1) * 2 + 1]);
            }
#pragma unroll
            for (int mf = 0; mf < 4; mf++) {
                uint32_t a[4];
                ldsm_x4(a, sAm + swz((a_row + mf * 16) * 64 + ks * 32 + a_kb));
#pragma unroll
                for (int nf = 0; nf < 4; nf++)
                    mma16816(acc[mf][nf], a,
                             bh[nf >> 1][(nf & 1) * 2], bh[nf >> 1][(nf & 1) * 2 + 1]);
            }
        }

        if (t + NSF - 1 < KT) load_stage(t + NSF - 1, nbuf);
        if (++buf == NSF) buf = 0;
        if (++nbuf == NSF) nbuf = 0;
    }

    const int er = lid >> 2;
    const int ec = (lid & 3) * 2;
#pragma unroll
    for (int mf = 0; mf < 4; mf++) {
#pragma unroll
        for (int nf = 0; nf < 4; nf++) {
            const int col = n0 + wn * 32 + nf * 8 + ec;
            const float bx = __ldg(&bias[col]);
            const float by = __ldg(&bias[col + 1]);
            const int r0 = m0 + wm * 64 + mf * 16 + er;
            const int r1 = r0 + 8;
            *(float2*)(C + (size_t)r0 * DIM + col) = make_float2(acc[mf][nf][0] + bx, acc[mf][nf][1] + by);
            *(float2*)(C + (size_t)r1 * DIM + col) = make_float2(acc[mf][nf][2] + bx, acc[mf][nf][3] + by);
        }
    }
}

// ---------------------------------------------------------------------------
// fp32 -> 2-way bf16 split
// ---------------------------------------------------------------------------
__global__ __launch_bounds__(256)
void split2_kernel(const float* __restrict__ in, __nv_bfloat16* __restrict__ h,
                   __nv_bfloat16* __restrict__ m, size_t n)
{
    size_t i = ((size_t)blockIdx.x * 256 + threadIdx.x) * 4;
    if (i >= n) return;
    float4 v = *(const float4*)(in + i);
    float vv[4] = {v.x, v.y, v.z, v.w};
    __nv_bfloat16 hh[4], mm[4];
#pragma unroll
    for (int j = 0; j < 4; j++) {
        float x = vv[j];
        __nv_bfloat16 a = __float2bfloat16(x);
        float r = x - __bfloat162float(a);
        mm[j] = __float2bfloat16(r);
        hh[j] = a;
    }
    *(__nv_bfloat162*)(h + i)     = __nv_bfloat162(hh[0], hh[1]);
    *(__nv_bfloat162*)(h + i + 2) = __nv_bfloat162(hh[2], hh[3]);
    *(__nv_bfloat162*)(m + i)     = __nv_bfloat162(mm[0], mm[1]);
    *(__nv_bfloat162*)(m + i + 2) = __nv_bfloat162(mm[2], mm[3]);
}

// ---------------------------------------------------------------------------
// block reduction of two floats (256 threads)
// ---------------------------------------------------------------------------
__device__ __forceinline__ float2 block_reduce2(float a, float b)
{
    __shared__ float sa[8], sb[8];
    __syncthreads();
    int lane = threadIdx.x & 31, wd = threadIdx.x >> 5;
#pragma unroll
    for (int o = 16; o; o >>= 1) {
        a += __shfl_down_sync(0xFFFFFFFFu, a, o);
        b += __shfl_down_sync(0xFFFFFFFFu, b, o);
    }
    if (lane == 0) { sa[wd] = a; sb[wd] = b; }
    __syncthreads();
    if (wd == 0) {
        a = (lane < 8) ? sa[lane] : 0.f;
        b = (lane < 8) ? sb[lane] : 0.f;
#pragma unroll
        for (int o = 4; o; o >>= 1) {
            a += __shfl_down_sync(0xFFFFFFFFu, a, o);
            b += __shfl_down_sync(0xFFFFFFFFu, b, o);
        }
        if (lane == 0) { sa[0] = a; sb[0] = b; }
    }
    __syncthreads();
    return make_float2(sa[0], sb[0]);
}

// ---------------------------------------------------------------------------
// LN + ReLU + head, 8 rows per block, params in registers, next-row prefetch.
// ---------------------------------------------------------------------------
template<bool SCATTER>
__global__ __launch_bounds__(256)
void ln_head8(const float* __restrict__ H,
              const float* __restrict__ gamma, const float* __restrict__ beta,
              const float* __restrict__ W2, const float* __restrict__ b2,
              const int* __restrict__ idx, const int* __restrict__ cnt_p,
              float* __restrict__ out)
{
    const int base = blockIdx.x * 8;
    int cnt = BATCH;
    if (SCATTER) {
        cnt = __ldg(cnt_p);
        if (base >= cnt) return;
    }
    const int t = threadIdx.x;

    const float4* g4  = (const float4*)gamma;
    const float4* be4 = (const float4*)beta;
    const float4* w04 = (const float4*)W2;
    const float4* w14 = (const float4*)(W2 + DIM);

    const float4 ga = g4[t*2],  gb = g4[t*2+1];
    const float4 ba = be4[t*2], bb = be4[t*2+1];
    const float4 wa = w04[t*2], wb = w04[t*2+1];
    const float4 wc = w14[t*2], wd = w14[t*2+1];
    const float bias0 = __ldg(&b2[0]), bias1 = __ldg(&b2[1]);
    const float inv_d = 1.f / (float)DIM;

    int rr0 = SCATTER ? min(base, cnt - 1) : base;
    const float4* h4 = (const float4*)(H + (size_t)rr0 * DIM);
    float4 v0 = h4[t*2];
    float4 v1 = h4[t*2+1];

#pragma unroll 1
    for (int r = 0; r < 8; r++) {
        const int row  = base + r;
        const bool act = !SCATTER || (row < cnt);

        float s  = v0.x + v0.y + v0.z + v0.w + v1.x + v1.y + v1.z + v1.w;
        float ss = v0.x*v0.x + v0.y*v0.y + v0.z*v0.z + v0.w*v0.w
                 + v1.x*v1.x + v1.y*v1.y + v1.z*v1.z + v1.w*v1.w;

        float4 n0v, n1v;
        if (r < 7) {
            const int nrow = base + r + 1;
            const int nrr  = SCATTER ? min(nrow, cnt - 1) : nrow;
            const float4* nh4 = (const float4*)(H + (size_t)nrr * DIM);
            n0v = nh4[t*2];
            n1v = nh4[t*2+1];
        }

        float2 red = block_reduce2(s, ss);
        float mu   = red.x * inv_d;
        float var  = red.y * inv_d - mu * mu;
        float rinv = rsqrtf(var + 1e-5f);

        float l0 = 0.f, l1 = 0.f, h;
        h = fmaxf(fmaf((v0.x - mu)*rinv, ga.x, ba.x), 0.f); l0 += h*wa.x; l1 += h*wc.x;
        h = fmaxf(fmaf((v0.y - mu)*rinv, ga.y, ba.y), 0.f); l0 += h*wa.y; l1 += h*wc.y;
        h = fmaxf(fmaf((v0.z - mu)*rinv, ga.z, ba.z), 0.f); l0 += h*wa.z; l1 += h*wc.z;
        h = fmaxf(fmaf((v0.w - mu)*rinv, ga.w, ba.w), 0.f); l0 += h*wa.w; l1 += h*wc.w;
        h = fmaxf(fmaf((v1.x - mu)*rinv, gb.x, bb.x), 0.f); l0 += h*wb.x; l1 += h*wd.x;
        h = fmaxf(fmaf((v1.y - mu)*rinv, gb.y, bb.y), 0.f); l0 += h*wb.y; l1 += h*wd.y;
        h = fmaxf(fmaf((v1.z - mu)*rinv, gb.z, bb.z), 0.f); l0 += h*wb.z; l1 += h*wd.z;
        h = fmaxf(fmaf((v1.w - mu)*rinv, gb.w, bb.w), 0.f); l0 += h*wb.w; l1 += h*wd.w;

        float2 lr = block_reduce2(l0, l1);
        if (t == 0 && act) {
            if (SCATTER) {
                const int o = __ldg(&idx[row]);
                out[o*2]   = lr.x + bias0;
                out[o*2+1] = lr.y + bias1;
            } else {
                out[row*2]   = lr.x + bias0;
                out[row*2+1] = lr.y + bias1;
            }
        }
        v0 = n0v;
        v1 = n1v;
    }
}

// ---------------------------------------------------------------------------
// Flag rows with |l0-l1| < thresh. Single block, ordered compaction.
// ---------------------------------------------------------------------------
__global__ __launch_bounds__(1024)
void flag_scan(const float* __restrict__ L0, float thresh, int cap,
               int* __restrict__ rlist, int* __restrict__ rcnt)
{
    __shared__ int sf[1024];
    const int t = threadIdx.x;
    uint32_t mask = 0;
    int c = 0;
#pragma unroll
    for (int j = 0; j < 32; j++) {
        const int b = t * 32 + j;
        float2 f = ((const float2*)L0)[b];
        const bool fl = fabsf(f.x - f.y) < thresh;
        mask |= (uint32_t)fl << j;
        c += fl;
    }
    sf[t] = c;
    __syncthreads();
    for (int off = 1; off < 1024; off <<= 1) {
        int v = (t >= off) ? sf[t - off] : 0;
        __syncthreads();
        sf[t] += v;
        __syncthreads();
    }
    int pos = sf[t] - c;
#pragma unroll
    for (int j = 0; j < 32; j++) {
        if ((mask >> j) & 1) {
            if (pos < cap) rlist[pos] = t * 32 + j;
            pos++;
        }
    }
    if (t == 1023) rcnt[0] = min(sf[1023], cap);
}

// ---------------------------------------------------------------------------
// Exact fp32 recompute of h = x@W1.T + b1 for flagged rows (column-parallel).
// ---------------------------------------------------------------------------
__global__ __launch_bounds__(256)
void refine_h(const float* __restrict__ x, const float* __restrict__ W1,
              const float* __restrict__ b1,
              const int* __restrict__ rlist, const int* __restrict__ rcnt,
              float* __restrict__ Hr)
{
    const int slot = blockIdx.y;
    if (slot >= __ldg(rcnt)) return;
    const int row = __ldg(&rlist[slot]);

    __shared__ float sx[DIM];
    const int tid = threadIdx.x, wid = tid >> 5, lane = tid & 31;
    for (int i = tid; i < DIM; i += 256) sx[i] = x[(size_t)row * DIM + i];
    __syncthreads();

    const int col0 = blockIdx.x * 64;
#pragma unroll 1
    for (int c = wid; c < 64; c += 8) {
        const int j = col0 + c;
        const float* wr = W1 + (size_t)j * DIM;
        float acc = 0.f;
#pragma unroll 8
        for (int k = lane; k < DIM; k += 32)
            acc = fmaf(sx[k], __ldg(&wr[k]), acc);
#pragma unroll
        for (int o = 16; o; o >>= 1) acc += __shfl_down_sync(0xFFFFFFFFu, acc, o);
        if (lane == 0) Hr[(size_t)slot * DIM + j] = acc + __ldg(&b1[j]);
    }
}

// LN + head from exact h; patch L[row]. One block per slot.
__global__ __launch_bounds__(256)
void refine_fix(const float* __restrict__ Hr,
                const float* __restrict__ gamma, const float* __restrict__ beta,
                const float* __restrict__ W2, const float* __restrict__ b2,
                const int* __restrict__ rlist, const int* __restrict__ rcnt,
                float* __restrict__ L)
{
    const int slot = blockIdx.x;
    if (slot >= __ldg(rcnt)) return;
    const int t = threadIdx.x;
    const float4* h4 = (const float4*)(Hr + (size_t)slot * DIM);
    float4 v0 = h4[t*2];
    float4 v1 = h4[t*2+1];

    float s  = v0.x+v0.y+v0.z+v0.w + v1.x+v1.y+v1.z+v1.w;
    float ss = v0.x*v0.x+v0.y*v0.y+v0.z*v0.z+v0.w*v0.w
             + v1.x*v1.x+v1.y*v1.y+v1.z*v1.z+v1.w*v1.w;
    float2 red = block_reduce2(s, ss);
    const float inv_d = 1.f / (float)DIM;
    float mu = red.x * inv_d, var = red.y * inv_d - mu * mu;
    float rinv = rsqrtf(var + 1e-5f);

    const float4* g4  = (const float4*)gamma;
    const float4* be4 = (const float4*)beta;
    const float4* w04 = (const float4*)W2;
    const float4* w14 = (const float4*)(W2 + DIM);

    float l0 = 0.f, l1 = 0.f;
#pragma unroll
    for (int q = 0; q < 2; q++) {
        float4 v  = q ? v1 : v0;
        float4 g  = g4[t*2+q], be = be4[t*2+q], wav = w04[t*2+q], wbv = w14[t*2+q];
        float h;
        h = fmaxf(fmaf((v.x - mu)*rinv, g.x, be.x), 0.f); l0 += h*wav.x; l1 += h*wbv.x;
        h = fmaxf(fmaf((v.y - mu)*rinv, g.y, be.y), 0.f); l0 += h*wav.y; l1 += h*wbv.y;
        h = fmaxf(fmaf((v.z - mu)*rinv, g.z, be.z), 0.f); l0 += h*wav.z; l1 += h*wbv.z;
        h = fmaxf(fmaf((v.w - mu)*rinv, g.w, be.w), 0.f); l0 += h*wav.w; l1 += h*wbv.w;
    }
    float2 lr = block_reduce2(l0, l1);
    if (t == 0) {
        const int row = __ldg(&rlist[slot]);
        L[row*2]   = lr.x + __ldg(&b2[0]);
        L[row*2+1] = lr.y + __ldg(&b2[1]);
    }
}

// ---------------------------------------------------------------------------
// Deterministic route compaction: 1 block, 1024 threads, 32 rows each.
// ---------------------------------------------------------------------------
__global__ __launch_bounds__(1024)
void route_scan(const float* __restrict__ L0, int* __restrict__ fake_idx,
                int* __restrict__ real_idx, int* __restrict__ cnts)
{
    __shared__ int sf[1024];
    const int t = threadIdx.x;
    uint32_t mask = 0;
    int c = 0;
#pragma unroll
    for (int j = 0; j < 32; j++) {
        const int b = t * 32 + j;
        float2 f = ((const float2*)L0)[b];
        const bool fake = (f.x >= f.y);
        mask |= (uint32_t)fake << j;
        c += fake;
    }
    sf[t] = c;
    __syncthreads();
    for (int off = 1; off < 1024; off <<= 1) {
        int v = (t >= off) ? sf[t - off] : 0;
        __syncthreads();
        sf[t] += v;
        __syncthreads();
    }
    const int total_fake = sf[1023];
    const int excl = sf[t] - c;
    int fpos = excl;
#pragma unroll
    for (int j = 0; j < 32; j++) {
        const int b = t * 32 + j;
        if ((mask >> j) & 1) {
            fake_idx[fpos++] = b;
        } else {
            const int fake_before = excl + __popc(mask & ((1u << j) - 1u));
            real_idx[b - fake_before] = b;
        }
    }
    if (t == 0) { cnts[0] = total_fake; cnts[1] = BATCH - total_fake; }
}

// ---------------------------------------------------------------------------
extern "C" void kernel_launch(void* const* d_in, const int* in_sizes, int n_in,
                              void* d_out, int out_size)
{
    (void)in_sizes; (void)n_in; (void)out_size;
    const float* x = (const float*)d_in[0];

    float *H = nullptr, *H2 = nullptr, *L = nullptr, *Hr = nullptr;
    __nv_bfloat16 *xs = nullptr, *ws = nullptr;
    int *idx = nullptr, *cnt = nullptr;
    int *rl1 = nullptr, *rc1 = nullptr, *rl2 = nullptr, *rc2 = nullptr;
    cudaGetSymbolAddress((void**)&H,   g_H);
    cudaGetSymbolAddress((void**)&H2,  g_H2);
    cudaGetSymbolAddress((void**)&L,   g_logits);
    cudaGetSymbolAddress((void**)&Hr,  g_Hr);
    cudaGetSymbolAddress((void**)&xs,  g_xs);
    cudaGetSymbolAddress((void**)&ws,  g_ws);
    cudaGetSymbolAddress((void**)&idx, g_idx);
    cudaGetSymbolAddress((void**)&cnt, g_cnt);
    cudaGetSymbolAddress((void**)&rl1, g_rlist1);
    cudaGetSymbolAddress((void**)&rc1, g_rcnt1);
    cudaGetSymbolAddress((void**)&rl2, g_rlist2);
    cudaGetSymbolAddress((void**)&rc2, g_rcnt2);

    const size_t XN = (size_t)BATCH * DIM;
    const size_t WN = (size_t)DIM * DIM;
    __nv_bfloat16 *xh = xs, *xm = xs + XN;
    // per-branch W split planes: ws[branch][plane]
    __nv_bfloat16 *w0h = ws,            *w0m = ws + WN;           // routing
    __nv_bfloat16 *w1h = ws + 2 * WN,   *w1m = ws + 3 * WN;       // fake
    __nv_bfloat16 *w2h = ws + 4 * WN,   *w2m = ws + 5 * WN;       // real

    constexpr int SMEM1 = NSTG * 16384;   // 96 KB
    constexpr int SMEM3 = NSF  * 32768;   // 96 KB
    cudaFuncSetAttribute(gemm_mma1,        cudaFuncAttributeMaxDynamicSharedMemorySize, SMEM1);
    cudaFuncSetAttribute(gemm_mma3f<true>, cudaFuncAttributeMaxDynamicSharedMemorySize, SMEM3);

    // one-time stream/event creation (host-side only; no device memory)
    static cudaStream_t s1 = nullptr;
    static cudaEvent_t evFork = nullptr, evWSplit = nullptr,
                       evRoute = nullptr, evJoin = nullptr;
    static bool streams_ok = false;
    if (!evJoin) {
        streams_ok =
            (cudaStreamCreateWithFlags(&s1, cudaStreamNonBlocking) == cudaSuccess) &&
            (cudaEventCreateWithFlags(&evFork,   cudaEventDisableTiming) == cudaSuccess) &&
            (cudaEventCreateWithFlags(&evWSplit, cudaEventDisableTiming) == cudaSuccess) &&
            (cudaEventCreateWithFlags(&evRoute,  cudaEventDisableTiming) == cudaSuccess) &&
            (cudaEventCreateWithFlags(&evJoin,   cudaEventDisableTiming) == cudaSuccess);
        if (!streams_ok) s1 = nullptr;
    }
    cudaStream_t sB = streams_ok ? s1 : (cudaStream_t)0;   // side stream (falls back to main)

    const float* fW1[3]; const float* fb1[3]; const float* flg[3];
    const float* flb[3]; const float* fW2[3]; const float* fb2[3];
    for (int br = 0; br < 3; br++) {
        fW1[br] = (const float*)d_in[1 + br * 6 + 0];
        fb1[br] = (const float*)d_in[1 + br * 6 + 1];
        flg[br] = (const float*)d_in[1 + br * 6 + 2];
        flb[br] = (const float*)d_in[1 + br * 6 + 3];
        fW2[br] = (const float*)d_in[1 + br * 6 + 4];
        fb2[br] = (const float*)d_in[1 + br * 6 + 5];
    }

    dim3 grid(DIM / 128, BATCH / 128);        // (16, 256)
    dim3 grid_t1(DIM / 128, RCAP1 / 128);     // (16, 64)

    // ---- fork: side stream splits fake/real W1 while routing chain runs ----
    if (streams_ok) {
        cudaEventRecord(evFork, 0);
        cudaStreamWaitEvent(sB, evFork, 0);
    }
    split2_kernel<<<(int)(WN / 4 / 256), 256, 0, sB>>>(fW1[1], w1h, w1m, WN);
    split2_kernel<<<(int)(WN / 4 / 256), 256, 0, sB>>>(fW1[2], w2h, w2m, WN);
    if (streams_ok) cudaEventRecord(evWSplit, sB);

    // ---- main stream: x split + routing branch (tiered precision) ----
    split2_kernel<<<(int)(XN / 4 / 256), 256>>>(x, xh, xm, XN);
    split2_kernel<<<(int)(WN / 4 / 256), 256>>>(fW1[0], w0h, w0m, WN);

    gemm_mma1<<<grid, 256, SMEM1>>>(xh, w0h, fb1[0], H);
    ln_head8<false><<<BATCH / 8, 256>>>(H, flg[0], flb[0], fW2[0], fb2[0],
                                        nullptr, nullptr, L);

    flag_scan<<<1, 1024>>>(L, 2e-2f, RCAP1, rl1, rc1);
    gemm_mma3f<true><<<grid_t1, 256, SMEM3>>>(xh, xm, w0h, w0m, fb1[0], H, rl1, rc1);
    ln_head8<true><<<RCAP1 / 8, 256>>>(H, flg[0], flb[0], fW2[0], fb2[0], rl1, rc1, L);

    flag_scan<<<1, 1024>>>(L, 1e-3f, RCAP2, rl2, rc2);
    refine_h<<<dim3(32, RCAP2), 256>>>(x, fW1[0], fb1[0], rl2, rc2, Hr);
    refine_fix<<<RCAP2, 256>>>(Hr, flg[0], flb[0], fW2[0], fb2[0], rl2, rc2, L);

    route_scan<<<1, 1024>>>(L, idx, idx + BATCH, cnt);

    if (streams_ok) {
        cudaEventRecord(evRoute, 0);
        cudaStreamWaitEvent(sB, evRoute, 0);   // real branch needs idx/cnt
        cudaStreamWaitEvent(0, evWSplit, 0);   // fake branch needs w1 splits
    }

    // ---- fake branch on main stream ----
    gemm_mma3f<true><<<grid, 256, SMEM3>>>(xh, xm, w1h, w1m, fb1[1], H,
                                           idx, cnt);
    ln_head8<true><<<BATCH / 8, 256>>>(H, flg[1], flb[1], fW2[1], fb2[1],
                                       idx, cnt, (float*)d_out);

    // ---- real branch on side stream (concurrent with fake) ----
    gemm_mma3f<true><<<grid, 256, SMEM3, sB>>>(xh, xm, w2h, w2m, fb1[2], H2,
                                               idx + BATCH, cnt + 1);
    ln_head8<true><<<BATCH / 8, 256, 0, sB>>>(H2, flg[2], flb[2], fW2[2], fb2[2],
                                              idx + BATCH, cnt + 1, (float*)d_out);

    if (streams_ok) {
        cudaEventRecord(evJoin, sB);
        cudaStreamWaitEvent(0, evJoin, 0);     // join before harness reads d_out
    }
}